// round 1
// baseline (speedup 1.0000x reference)
#include <cuda_runtime.h>
#include <cuda_bf16.h>
#include <math.h>

// Problem constants
#define B_  2
#define T_  2048
#define DM_ 2048          // d_model
#define H_  16
#define HD_ 128
#define TOT_ 2048         // H*HD
#define MROWS 4096        // B*T
#define MAIN_ELEMS (MROWS * DM_)   // 8388608

// ---------------- scratch (device globals; no allocation allowed) ----------------
__device__ float g_tq[MROWS * TOT_];   // x@Wq  [b*t, h*hd]
__device__ float g_tk[MROWS * TOT_];
__device__ float g_tv[MROWS * TOT_];
__device__ float g_Q[MROWS * TOT_];    // roped, [b,h,t,hd]
__device__ float g_K[MROWS * TOT_];
__device__ float g_V[MROWS * TOT_];
__device__ float g_O[MROWS * TOT_];    // attention out, [b,t,h*hd]

// ---------------- SGEMM: C[M,N] = A[M,K] @ B[K,N], all row-major, fp32 ----------------
// M=4096, N=2048, K=2048 fixed. 128x128 tile, BK=16, 256 threads, 8x8 per thread.
__global__ __launch_bounds__(256) void sgemm128(const float* __restrict__ A,
                                                const float* __restrict__ Bm,
                                                float* __restrict__ C) {
    const int N = 2048, K = 2048;
    __shared__ float As[16][128];
    __shared__ float Bs[16][128];
    const int tid = threadIdx.x;
    const int tx = tid & 15, ty = tid >> 4;
    const int m0 = blockIdx.y * 128, n0 = blockIdx.x * 128;

    float acc[8][8];
#pragma unroll
    for (int i = 0; i < 8; ++i)
#pragma unroll
        for (int j = 0; j < 8; ++j) acc[i][j] = 0.f;

    for (int k0 = 0; k0 < K; k0 += 16) {
        // load A tile (128 rows x 16 cols) -> transposed into As[16][128]
#pragma unroll
        for (int q = 0; q < 2; ++q) {
            int f = tid + q * 256;               // 0..511 float4s
            int r = f >> 2, cb = (f & 3) << 2;
            float4 a = *(const float4*)&A[(size_t)(m0 + r) * K + k0 + cb];
            As[cb + 0][r] = a.x; As[cb + 1][r] = a.y;
            As[cb + 2][r] = a.z; As[cb + 3][r] = a.w;
        }
        // load B tile (16 rows x 128 cols)
#pragma unroll
        for (int q = 0; q < 2; ++q) {
            int f = tid + q * 256;
            int r = f >> 5, cb = (f & 31) << 2;
            *(float4*)&Bs[r][cb] = *(const float4*)&Bm[(size_t)(k0 + r) * N + n0 + cb];
        }
        __syncthreads();

#pragma unroll
        for (int kk = 0; kk < 16; ++kk) {
            float a[8], b[8];
            *(float4*)&a[0] = *(float4*)&As[kk][ty * 8];
            *(float4*)&a[4] = *(float4*)&As[kk][ty * 8 + 4];
            *(float4*)&b[0] = *(float4*)&Bs[kk][tx * 8];
            *(float4*)&b[4] = *(float4*)&Bs[kk][tx * 8 + 4];
#pragma unroll
            for (int i = 0; i < 8; ++i)
#pragma unroll
                for (int j = 0; j < 8; ++j)
                    acc[i][j] = fmaf(a[i], b[j], acc[i][j]);
        }
        __syncthreads();
    }

#pragma unroll
    for (int i = 0; i < 8; ++i) {
        float* cp = &C[(size_t)(m0 + ty * 8 + i) * N + n0 + tx * 8];
        *(float4*)&cp[0] = make_float4(acc[i][0], acc[i][1], acc[i][2], acc[i][3]);
        *(float4*)&cp[4] = make_float4(acc[i][4], acc[i][5], acc[i][6], acc[i][7]);
    }
}

// ---------------- RoPE + permute [b,t,h,hd] -> [b,h,t,hd]; also emit K,V outputs ----------------
__global__ __launch_bounds__(256) void rope_permute(const float* __restrict__ tq,
                                                    const float* __restrict__ tk,
                                                    const float* __restrict__ tv,
                                                    const float* __restrict__ cosp,
                                                    const float* __restrict__ sinp,
                                                    float* __restrict__ Qh,
                                                    float* __restrict__ Kh,
                                                    float* __restrict__ Vh,
                                                    float* __restrict__ outK,
                                                    float* __restrict__ outV,
                                                    int writeKV) {
    int idx = blockIdx.x * blockDim.x + threadIdx.x;   // B*T*H*64 threads
    int d = idx & 63;
    int h = (idx >> 6) & 15;
    int t = (idx >> 10) & 2047;
    int b = idx >> 21;

    size_t in0 = ((size_t)(b * T_ + t)) * TOT_ + h * HD_;
    size_t ob  = (((size_t)(b * H_ + h)) * T_ + t) * HD_;

    float c1 = cosp[t * HD_ + d],      s1 = sinp[t * HD_ + d];
    float c2 = cosp[t * HD_ + d + 64], s2 = sinp[t * HD_ + d + 64];

    float q1 = tq[in0 + d], q2 = tq[in0 + d + 64];
    Qh[ob + d]      = q1 * c1 - q2 * s1;
    Qh[ob + d + 64] = q2 * c2 + q1 * s2;

    float k1 = tk[in0 + d], k2 = tk[in0 + d + 64];
    float ko1 = k1 * c1 - k2 * s1;
    float ko2 = k2 * c2 + k1 * s2;
    Kh[ob + d] = ko1; Kh[ob + d + 64] = ko2;

    float v1 = tv[in0 + d], v2 = tv[in0 + d + 64];
    Vh[ob + d] = v1; Vh[ob + d + 64] = v2;

    if (writeKV) {
        outK[ob + d] = ko1; outK[ob + d + 64] = ko2;
        outV[ob + d] = v1;  outV[ob + d + 64] = v2;
    }
}

// ---------------- Flash attention, causal, fp32 ----------------
// Grid: (T/64, B*H). Block 256 threads as 16x16. BM=BN=64, HD=128.
// smem: Qs[64][132] + Kt[128][68] + Vs[64][132] + Ps[64][68]
#define FA_SMEM ((64*132 + 128*68 + 64*132 + 64*68) * 4)

__global__ __launch_bounds__(256) void flash_attn(const float* __restrict__ Q,
                                                  const float* __restrict__ K,
                                                  const float* __restrict__ V,
                                                  float* __restrict__ O) {
    const int qt = blockIdx.x;
    const int bh = blockIdx.y;
    const int b = bh / H_, h = bh % H_;
    const int m0 = qt * 64;
    const size_t base = (size_t)bh * T_ * HD_;

    extern __shared__ float sm[];
    float* Qs = sm;                 // 64 x 132
    float* Kt = Qs + 64 * 132;      // 128 x 68 (transposed: [d][n])
    float* Vs = Kt + 128 * 68;      // 64 x 132
    float* Ps = Vs + 64 * 132;      // 64 x 68

    const int tid = threadIdx.x;
    const int tx = tid & 15, ty = tid >> 4;

    // load Q tile
    for (int i4 = tid; i4 < 64 * 32; i4 += 256) {
        int r = i4 >> 5, c = (i4 & 31) << 2;
        *(float4*)&Qs[r * 132 + c] = *(const float4*)&Q[base + (size_t)(m0 + r) * HD_ + c];
    }

    float o[4][8];
#pragma unroll
    for (int i = 0; i < 4; ++i)
#pragma unroll
        for (int c = 0; c < 8; ++c) o[i][c] = 0.f;
    float m_i[4] = {-1e30f, -1e30f, -1e30f, -1e30f};
    float l_i[4] = {0.f, 0.f, 0.f, 0.f};

    const float scale = 0.08838834764831843f;   // 128^-0.5
    const int ntiles = qt + 1;

    for (int tt = 0; tt < ntiles; ++tt) {
        const int n0 = tt * 64;
        __syncthreads();   // Kt/Vs safe to overwrite; also makes Qs visible on first iter
        // K tile transposed into Kt[d][n]
        for (int i = tid; i < 64 * 128; i += 256) {
            int r = i >> 7, c = i & 127;
            Kt[c * 68 + r] = K[base + (size_t)(n0 + r) * HD_ + c];
        }
        // V tile
        for (int i4 = tid; i4 < 64 * 32; i4 += 256) {
            int r = i4 >> 5, c = (i4 & 31) << 2;
            *(float4*)&Vs[r * 132 + c] = *(const float4*)&V[base + (size_t)(n0 + r) * HD_ + c];
        }
        __syncthreads();

        // S = Q @ K^T for 4x4 subtile
        float s[4][4];
#pragma unroll
        for (int i = 0; i < 4; ++i)
#pragma unroll
            for (int j = 0; j < 4; ++j) s[i][j] = 0.f;

#pragma unroll 8
        for (int d = 0; d < 128; d += 4) {
            float qv[4][4], kv[4][4];
#pragma unroll
            for (int i = 0; i < 4; ++i)
                *(float4*)&qv[i][0] = *(float4*)&Qs[(ty * 4 + i) * 132 + d];
#pragma unroll
            for (int u = 0; u < 4; ++u)
                *(float4*)&kv[u][0] = *(float4*)&Kt[(d + u) * 68 + tx * 4];
#pragma unroll
            for (int u = 0; u < 4; ++u)
#pragma unroll
                for (int i = 0; i < 4; ++i)
#pragma unroll
                    for (int j = 0; j < 4; ++j)
                        s[i][j] = fmaf(qv[i][u], kv[u][j], s[i][j]);
        }

        // scale + causal mask + online softmax
        const int qi0 = m0 + ty * 4;
        const int kj0 = n0 + tx * 4;
#pragma unroll
        for (int i = 0; i < 4; ++i) {
#pragma unroll
            for (int j = 0; j < 4; ++j) {
                float v = s[i][j] * scale;
                if (kj0 + j > qi0 + i) v = -1e30f;
                s[i][j] = v;
            }
            float mt = fmaxf(fmaxf(s[i][0], s[i][1]), fmaxf(s[i][2], s[i][3]));
#pragma unroll
            for (int w = 8; w > 0; w >>= 1)
                mt = fmaxf(mt, __shfl_xor_sync(0xffffffffu, mt, w));
            float m_new = fmaxf(m_i[i], mt);
            float alpha = __expf(m_i[i] - m_new);
            float rs = 0.f;
#pragma unroll
            for (int j = 0; j < 4; ++j) {
                float p = __expf(s[i][j] - m_new);
                s[i][j] = p;
                rs += p;
            }
#pragma unroll
            for (int w = 8; w > 0; w >>= 1)
                rs += __shfl_xor_sync(0xffffffffu, rs, w);
            l_i[i] = l_i[i] * alpha + rs;
            m_i[i] = m_new;
#pragma unroll
            for (int c = 0; c < 8; ++c) o[i][c] *= alpha;
            *(float4*)&Ps[(ty * 4 + i) * 68 + tx * 4] =
                make_float4(s[i][0], s[i][1], s[i][2], s[i][3]);
        }
        __syncthreads();

        // O += P @ V
#pragma unroll 4
        for (int n = 0; n < 64; n += 4) {
            float pv[4][4], vv[4][8];
#pragma unroll
            for (int i = 0; i < 4; ++i)
                *(float4*)&pv[i][0] = *(float4*)&Ps[(ty * 4 + i) * 68 + n];
#pragma unroll
            for (int u = 0; u < 4; ++u) {
                *(float4*)&vv[u][0] = *(float4*)&Vs[(n + u) * 132 + tx * 8];
                *(float4*)&vv[u][4] = *(float4*)&Vs[(n + u) * 132 + tx * 8 + 4];
            }
#pragma unroll
            for (int u = 0; u < 4; ++u)
#pragma unroll
                for (int i = 0; i < 4; ++i)
#pragma unroll
                    for (int c = 0; c < 8; ++c)
                        o[i][c] = fmaf(pv[i][u], vv[u][c], o[i][c]);
        }
    }

    // finalize: O /= l, write to [b, t, h*HD]
#pragma unroll
    for (int i = 0; i < 4; ++i) {
        float inv = 1.f / l_i[i];
        int trow = m0 + ty * 4 + i;
        float* op = &O[((size_t)(b * T_ + trow)) * TOT_ + h * HD_ + tx * 8];
        *(float4*)&op[0] = make_float4(o[i][0] * inv, o[i][1] * inv, o[i][2] * inv, o[i][3] * inv);
        *(float4*)&op[4] = make_float4(o[i][4] * inv, o[i][5] * inv, o[i][6] * inv, o[i][7] * inv);
    }
}

// ---------------- launch ----------------
extern "C" void kernel_launch(void* const* d_in, const int* in_sizes, int n_in,
                              void* d_out, int out_size) {
    const float* x   = (const float*)d_in[0];
    const float* cs  = (const float*)d_in[1];
    const float* sn  = (const float*)d_in[2];
    const float* Wq  = (const float*)d_in[3];
    const float* Wk  = (const float*)d_in[4];
    const float* Wv  = (const float*)d_in[5];
    const float* Wo  = (const float*)d_in[6];
    float* out = (float*)d_out;

    float *tq, *tk, *tv, *Qh, *Kh, *Vh, *Og;
    cudaGetSymbolAddress((void**)&tq, g_tq);
    cudaGetSymbolAddress((void**)&tk, g_tk);
    cudaGetSymbolAddress((void**)&tv, g_tv);
    cudaGetSymbolAddress((void**)&Qh, g_Q);
    cudaGetSymbolAddress((void**)&Kh, g_K);
    cudaGetSymbolAddress((void**)&Vh, g_V);
    cudaGetSymbolAddress((void**)&Og, g_O);

    dim3 gemmGrid(TOT_ / 128, MROWS / 128);   // (16, 32)
    sgemm128<<<gemmGrid, 256>>>(x, Wq, tq);
    sgemm128<<<gemmGrid, 256>>>(x, Wk, tk);
    sgemm128<<<gemmGrid, 256>>>(x, Wv, tv);

    int writeKV = (out_size >= 3 * MAIN_ELEMS) ? 1 : 0;
    float* outK = out + MAIN_ELEMS;
    float* outV = out + 2 * MAIN_ELEMS;
    int ropeThreads = B_ * T_ * H_ * 64;      // 4,194,304
    rope_permute<<<ropeThreads / 256, 256>>>(tq, tk, tv, cs, sn, Qh, Kh, Vh,
                                             writeKV ? outK : Qh,
                                             writeKV ? outV : Qh, writeKV);

    cudaFuncSetAttribute(flash_attn, cudaFuncAttributeMaxDynamicSharedMemorySize, FA_SMEM);
    dim3 faGrid(T_ / 64, B_ * H_);            // (32, 32)
    flash_attn<<<faGrid, 256, FA_SMEM>>>(Qh, Kh, Vh, Og);

    sgemm128<<<gemmGrid, 256>>>(Og, Wo, out);
}

// round 3
// speedup vs baseline: 1.5680x; 1.5680x over previous
#include <cuda_runtime.h>
#include <cuda_bf16.h>
#include <math.h>

// Problem constants
#define B_  2
#define T_  2048
#define DM_ 2048
#define H_  16
#define HD_ 128
#define TOT_ 2048
#define MROWS 4096
#define NQKV 6144
#define MAIN_ELEMS (MROWS * DM_)

// ---------------- scratch ----------------
__device__ float g_qkv[MROWS * NQKV];        // fused QKV proj output [b*t][6144]
__device__ float g_Q[MROWS * TOT_];          // roped [b,h,t,hd]
__device__ float g_K[MROWS * TOT_];
__device__ float g_V[MROWS * TOT_];
__device__ float g_O[MROWS * TOT_];          // attention out [b,t,h*hd]
__device__ __align__(16) __nv_bfloat16 g_xh[MROWS * DM_],  g_xl[MROWS * DM_];
__device__ __align__(16) __nv_bfloat16 g_wqh[DM_ * NQKV],  g_wql[DM_ * NQKV];
__device__ __align__(16) __nv_bfloat16 g_woh[TOT_ * DM_],  g_wol[TOT_ * DM_];
__device__ __align__(16) __nv_bfloat16 g_oh[MROWS * TOT_], g_ol[MROWS * TOT_];

// ---------------- split fp32 -> (hi, lo) bf16 ----------------
__device__ __forceinline__ void split1(float v, unsigned short& h, unsigned short& l) {
    __nv_bfloat16 hb = __float2bfloat16(v);
    __nv_bfloat16 lb = __float2bfloat16(v - __bfloat162float(hb));
    h = __bfloat16_as_ushort(hb);
    l = __bfloat16_as_ushort(lb);
}

__global__ __launch_bounds__(256) void split_f32(const float* __restrict__ src,
                                                 __nv_bfloat16* __restrict__ hi,
                                                 __nv_bfloat16* __restrict__ lo, int n4) {
    int i = blockIdx.x * blockDim.x + threadIdx.x;
    if (i >= n4) return;
    float4 v = ((const float4*)src)[i];
    unsigned short h0,h1,h2,h3,l0,l1,l2,l3;
    split1(v.x,h0,l0); split1(v.y,h1,l1); split1(v.z,h2,l2); split1(v.w,h3,l3);
    uint2 uh, ul;
    uh.x = (unsigned)h0 | ((unsigned)h1 << 16); uh.y = (unsigned)h2 | ((unsigned)h3 << 16);
    ul.x = (unsigned)l0 | ((unsigned)l1 << 16); ul.y = (unsigned)l2 | ((unsigned)l3 << 16);
    ((uint2*)hi)[i] = uh;
    ((uint2*)lo)[i] = ul;
}

// fuse Wq|Wk|Wv -> [2048][6144] split
__global__ __launch_bounds__(256) void split_wqkv(const float* __restrict__ Wq,
                                                  const float* __restrict__ Wk,
                                                  const float* __restrict__ Wv,
                                                  __nv_bfloat16* __restrict__ hi,
                                                  __nv_bfloat16* __restrict__ lo) {
    int i = blockIdx.x * blockDim.x + threadIdx.x;
    if (i >= DM_ * NQKV / 4) return;
    int k = i / (NQKV / 4);
    int n = (i % (NQKV / 4)) * 4;
    const float* src;
    int nn;
    if (n < 2048)       { src = Wq; nn = n; }
    else if (n < 4096)  { src = Wk; nn = n - 2048; }
    else                { src = Wv; nn = n - 4096; }
    float4 v = *(const float4*)&src[(size_t)k * 2048 + nn];
    unsigned short h0,h1,h2,h3,l0,l1,l2,l3;
    split1(v.x,h0,l0); split1(v.y,h1,l1); split1(v.z,h2,l2); split1(v.w,h3,l3);
    uint2 uh, ul;
    uh.x = (unsigned)h0 | ((unsigned)h1 << 16); uh.y = (unsigned)h2 | ((unsigned)h3 << 16);
    ul.x = (unsigned)l0 | ((unsigned)l1 << 16); ul.y = (unsigned)l2 | ((unsigned)l3 << 16);
    ((uint2*)hi)[i] = uh;
    ((uint2*)lo)[i] = ul;
}

// ---------------- BF16x3 tensor-core GEMM ----------------
// C[M,N] = A[M,2048] @ B[2048,N]; (Ah+Al)(Bh+Bl) ~ AhBh + AhBl + AlBh
// BM=128 BN=128 BK=32, 256 threads = 8 warps (4 in M x 2 in N), warp tile 32x64.
// Padding MUST be multiples of 8 bf16 (16B) so every ldmatrix row address is 16B-aligned.
#define GK 2048
#define LDA 40      // BK+8 (bf16 elems) -> 80 B/row (16B multiple)
#define LDB 136     // BN+8              -> 272 B/row (16B multiple)
#define STG_AH 0
#define STG_AL 5120            // 128*40
#define STG_BH 10240
#define STG_BL 14592           // 10240 + 32*136
#define STG_SZ 18944           // bf16 elems per stage (37888 B)
#define GEMM_SMEM (2 * STG_SZ * 2)   // 75776 bytes

__device__ __forceinline__ void ldsm_x4(unsigned& r0, unsigned& r1, unsigned& r2, unsigned& r3,
                                        unsigned addr) {
    asm volatile("ldmatrix.sync.aligned.m8n8.x4.shared.b16 {%0,%1,%2,%3}, [%4];\n"
                 : "=r"(r0), "=r"(r1), "=r"(r2), "=r"(r3) : "r"(addr));
}
__device__ __forceinline__ void ldsm_x4t(unsigned& r0, unsigned& r1, unsigned& r2, unsigned& r3,
                                         unsigned addr) {
    asm volatile("ldmatrix.sync.aligned.m8n8.x4.trans.shared.b16 {%0,%1,%2,%3}, [%4];\n"
                 : "=r"(r0), "=r"(r1), "=r"(r2), "=r"(r3) : "r"(addr));
}
__device__ __forceinline__ void mma16816(float* c, const unsigned* a, const unsigned* b) {
    asm volatile("mma.sync.aligned.m16n8k16.row.col.f32.bf16.bf16.f32 "
                 "{%0,%1,%2,%3}, {%4,%5,%6,%7}, {%8,%9}, {%0,%1,%2,%3};\n"
                 : "+f"(c[0]), "+f"(c[1]), "+f"(c[2]), "+f"(c[3])
                 : "r"(a[0]), "r"(a[1]), "r"(a[2]), "r"(a[3]), "r"(b[0]), "r"(b[1]));
}

__global__ __launch_bounds__(256) void gemm_bf16x3(const __nv_bfloat16* __restrict__ Ah,
                                                   const __nv_bfloat16* __restrict__ Al,
                                                   const __nv_bfloat16* __restrict__ Bh,
                                                   const __nv_bfloat16* __restrict__ Bl,
                                                   float* __restrict__ C, int N) {
    extern __shared__ __nv_bfloat16 sm[];
    const int tid = threadIdx.x;
    const int lane = tid & 31, wid = tid >> 5;
    const int wm = wid & 3, wn = wid >> 2;      // warp tile origin: (wm*32, wn*64)
    const int m0 = blockIdx.y * 128, n0 = blockIdx.x * 128;

    uint4 ra_h[2], ra_l[2], rb_h[2], rb_l[2];
    int ar[2], ac[2], br[2], bc[2];
#pragma unroll
    for (int q = 0; q < 2; ++q) {
        int c = tid * 2 + q;
        ar[q] = c >> 2;  ac[q] = (c & 3) << 3;   // A: 128 rows x 32 cols
        br[q] = c >> 4;  bc[q] = (c & 15) << 3;  // B: 32 rows x 128 cols
    }

    float acc[2][8][4];
#pragma unroll
    for (int mt = 0; mt < 2; ++mt)
#pragma unroll
        for (int nt = 0; nt < 8; ++nt)
#pragma unroll
            for (int e = 0; e < 4; ++e) acc[mt][nt][e] = 0.f;

    auto load_regs = [&](int k0) {
#pragma unroll
        for (int q = 0; q < 2; ++q) {
            size_t aoff = (size_t)(m0 + ar[q]) * GK + k0 + ac[q];
            size_t boff = (size_t)(k0 + br[q]) * N + n0 + bc[q];
            ra_h[q] = *(const uint4*)(Ah + aoff);
            ra_l[q] = *(const uint4*)(Al + aoff);
            rb_h[q] = *(const uint4*)(Bh + boff);
            rb_l[q] = *(const uint4*)(Bl + boff);
        }
    };
    auto store_stage = [&](int s) {
        __nv_bfloat16* base = sm + s * STG_SZ;
#pragma unroll
        for (int q = 0; q < 2; ++q) {
            int ao = ar[q] * LDA + ac[q];
            int bo = br[q] * LDB + bc[q];
            *(uint4*)(base + STG_AH + ao) = ra_h[q];
            *(uint4*)(base + STG_AL + ao) = ra_l[q];
            *(uint4*)(base + STG_BH + bo) = rb_h[q];
            *(uint4*)(base + STG_BL + bo) = rb_l[q];
        }
    };

    load_regs(0);
    store_stage(0);
    __syncthreads();

    const int lrow = lane & 15;
    const int lcol = (lane >> 4) << 3;

    for (int it = 0; it < GK / 32; ++it) {
        if (it < GK / 32 - 1) load_regs((it + 1) * 32);

        const __nv_bfloat16* base = sm + (it & 1) * STG_SZ;
        unsigned s_ah = (unsigned)__cvta_generic_to_shared(base + STG_AH);
        unsigned s_al = (unsigned)__cvta_generic_to_shared(base + STG_AL);
        unsigned s_bh = (unsigned)__cvta_generic_to_shared(base + STG_BH);
        unsigned s_bl = (unsigned)__cvta_generic_to_shared(base + STG_BL);

#pragma unroll
        for (int ks = 0; ks < 32; ks += 16) {
            unsigned a_h[2][4], a_l[2][4];
#pragma unroll
            for (int mt = 0; mt < 2; ++mt) {
                unsigned off = ((wm * 32 + mt * 16 + lrow) * LDA + ks + lcol) * 2;
                ldsm_x4(a_h[mt][0], a_h[mt][1], a_h[mt][2], a_h[mt][3], s_ah + off);
                ldsm_x4(a_l[mt][0], a_l[mt][1], a_l[mt][2], a_l[mt][3], s_al + off);
            }
            unsigned b_h[8][2], b_l[8][2];
#pragma unroll
            for (int nt2 = 0; nt2 < 4; ++nt2) {
                unsigned off = ((ks + lrow) * LDB + wn * 64 + nt2 * 16 + lcol) * 2;
                unsigned t0, t1, t2, t3;
                ldsm_x4t(t0, t1, t2, t3, s_bh + off);
                b_h[2*nt2][0] = t0; b_h[2*nt2][1] = t1;
                b_h[2*nt2+1][0] = t2; b_h[2*nt2+1][1] = t3;
                ldsm_x4t(t0, t1, t2, t3, s_bl + off);
                b_l[2*nt2][0] = t0; b_l[2*nt2][1] = t1;
                b_l[2*nt2+1][0] = t2; b_l[2*nt2+1][1] = t3;
            }
#pragma unroll
            for (int mt = 0; mt < 2; ++mt)
#pragma unroll
                for (int nt = 0; nt < 8; ++nt) {
                    mma16816(acc[mt][nt], a_h[mt], b_h[nt]);
                    mma16816(acc[mt][nt], a_h[mt], b_l[nt]);
                    mma16816(acc[mt][nt], a_l[mt], b_h[nt]);
                }
        }
        if (it < GK / 32 - 1) store_stage((it + 1) & 1);
        __syncthreads();
    }

    // epilogue
    const int erow = lane >> 2;
    const int ecol = (lane & 3) << 1;
#pragma unroll
    for (int mt = 0; mt < 2; ++mt)
#pragma unroll
        for (int nt = 0; nt < 8; ++nt) {
            int gr = m0 + wm * 32 + mt * 16 + erow;
            int gc = n0 + wn * 64 + nt * 8 + ecol;
            *(float2*)&C[(size_t)gr * N + gc]       = make_float2(acc[mt][nt][0], acc[mt][nt][1]);
            *(float2*)&C[(size_t)(gr + 8) * N + gc] = make_float2(acc[mt][nt][2], acc[mt][nt][3]);
        }
}

// ---------------- RoPE + permute (reads fused qkv [b*t][6144]) ----------------
__global__ __launch_bounds__(256) void rope_permute(const float* __restrict__ qkv,
                                                    const float* __restrict__ cosp,
                                                    const float* __restrict__ sinp,
                                                    float* __restrict__ Qh,
                                                    float* __restrict__ Kh,
                                                    float* __restrict__ Vh,
                                                    float* __restrict__ outK,
                                                    float* __restrict__ outV,
                                                    int writeKV) {
    int idx = blockIdx.x * blockDim.x + threadIdx.x;
    int d = idx & 63;
    int h = (idx >> 6) & 15;
    int t = (idx >> 10) & 2047;
    int b = idx >> 21;

    size_t in0 = ((size_t)(b * T_ + t)) * NQKV + h * HD_;
    size_t ob  = (((size_t)(b * H_ + h)) * T_ + t) * HD_;

    float c1 = cosp[t * HD_ + d],      s1 = sinp[t * HD_ + d];
    float c2 = cosp[t * HD_ + d + 64], s2 = sinp[t * HD_ + d + 64];

    float q1 = qkv[in0 + d], q2 = qkv[in0 + d + 64];
    Qh[ob + d]      = q1 * c1 - q2 * s1;
    Qh[ob + d + 64] = q2 * c2 + q1 * s2;

    float k1 = qkv[in0 + 2048 + d], k2 = qkv[in0 + 2048 + d + 64];
    float ko1 = k1 * c1 - k2 * s1;
    float ko2 = k2 * c2 + k1 * s2;
    Kh[ob + d] = ko1; Kh[ob + d + 64] = ko2;

    float v1 = qkv[in0 + 4096 + d], v2 = qkv[in0 + 4096 + d + 64];
    Vh[ob + d] = v1; Vh[ob + d + 64] = v2;

    if (writeKV) {
        outK[ob + d] = ko1; outK[ob + d + 64] = ko2;
        outV[ob + d] = v1;  outV[ob + d + 64] = v2;
    }
}

// ---------------- Flash attention, causal, fp32 ----------------
#define FA_SMEM ((64*132 + 128*68 + 64*132 + 64*68) * 4)

__global__ __launch_bounds__(256) void flash_attn(const float* __restrict__ Q,
                                                  const float* __restrict__ K,
                                                  const float* __restrict__ V,
                                                  float* __restrict__ O) {
    const int qt = blockIdx.x;
    const int bh = blockIdx.y;
    const int b = bh / H_, h = bh % H_;
    const int m0 = qt * 64;
    const size_t base = (size_t)bh * T_ * HD_;

    extern __shared__ float smf[];
    float* Qs = smf;
    float* Kt = Qs + 64 * 132;
    float* Vs = Kt + 128 * 68;
    float* Ps = Vs + 64 * 132;

    const int tid = threadIdx.x;
    const int tx = tid & 15, ty = tid >> 4;

    for (int i4 = tid; i4 < 64 * 32; i4 += 256) {
        int r = i4 >> 5, c = (i4 & 31) << 2;
        *(float4*)&Qs[r * 132 + c] = *(const float4*)&Q[base + (size_t)(m0 + r) * HD_ + c];
    }

    float o[4][8];
#pragma unroll
    for (int i = 0; i < 4; ++i)
#pragma unroll
        for (int c = 0; c < 8; ++c) o[i][c] = 0.f;
    float m_i[4] = {-1e30f, -1e30f, -1e30f, -1e30f};
    float l_i[4] = {0.f, 0.f, 0.f, 0.f};

    const float scale = 0.08838834764831843f;
    const int ntiles = qt + 1;

    for (int tt = 0; tt < ntiles; ++tt) {
        const int n0 = tt * 64;
        __syncthreads();
        for (int i = tid; i < 64 * 128; i += 256) {
            int r = i >> 7, c = i & 127;
            Kt[c * 68 + r] = K[base + (size_t)(n0 + r) * HD_ + c];
        }
        for (int i4 = tid; i4 < 64 * 32; i4 += 256) {
            int r = i4 >> 5, c = (i4 & 31) << 2;
            *(float4*)&Vs[r * 132 + c] = *(const float4*)&V[base + (size_t)(n0 + r) * HD_ + c];
        }
        __syncthreads();

        float s[4][4];
#pragma unroll
        for (int i = 0; i < 4; ++i)
#pragma unroll
            for (int j = 0; j < 4; ++j) s[i][j] = 0.f;

#pragma unroll 8
        for (int d = 0; d < 128; d += 4) {
            float qv[4][4], kv[4][4];
#pragma unroll
            for (int i = 0; i < 4; ++i)
                *(float4*)&qv[i][0] = *(float4*)&Qs[(ty * 4 + i) * 132 + d];
#pragma unroll
            for (int u = 0; u < 4; ++u)
                *(float4*)&kv[u][0] = *(float4*)&Kt[(d + u) * 68 + tx * 4];
#pragma unroll
            for (int u = 0; u < 4; ++u)
#pragma unroll
                for (int i = 0; i < 4; ++i)
#pragma unroll
                    for (int j = 0; j < 4; ++j)
                        s[i][j] = fmaf(qv[i][u], kv[u][j], s[i][j]);
        }

        const int qi0 = m0 + ty * 4;
        const int kj0 = n0 + tx * 4;
#pragma unroll
        for (int i = 0; i < 4; ++i) {
#pragma unroll
            for (int j = 0; j < 4; ++j) {
                float v = s[i][j] * scale;
                if (kj0 + j > qi0 + i) v = -1e30f;
                s[i][j] = v;
            }
            float mt = fmaxf(fmaxf(s[i][0], s[i][1]), fmaxf(s[i][2], s[i][3]));
#pragma unroll
            for (int w = 8; w > 0; w >>= 1)
                mt = fmaxf(mt, __shfl_xor_sync(0xffffffffu, mt, w));
            float m_new = fmaxf(m_i[i], mt);
            float alpha = __expf(m_i[i] - m_new);
            float rs = 0.f;
#pragma unroll
            for (int j = 0; j < 4; ++j) {
                float p = __expf(s[i][j] - m_new);
                s[i][j] = p;
                rs += p;
            }
#pragma unroll
            for (int w = 8; w > 0; w >>= 1)
                rs += __shfl_xor_sync(0xffffffffu, rs, w);
            l_i[i] = l_i[i] * alpha + rs;
            m_i[i] = m_new;
#pragma unroll
            for (int c = 0; c < 8; ++c) o[i][c] *= alpha;
            *(float4*)&Ps[(ty * 4 + i) * 68 + tx * 4] =
                make_float4(s[i][0], s[i][1], s[i][2], s[i][3]);
        }
        __syncthreads();

#pragma unroll 4
        for (int n = 0; n < 64; n += 4) {
            float pv[4][4], vv[4][8];
#pragma unroll
            for (int i = 0; i < 4; ++i)
                *(float4*)&pv[i][0] = *(float4*)&Ps[(ty * 4 + i) * 68 + n];
#pragma unroll
            for (int u = 0; u < 4; ++u) {
                *(float4*)&vv[u][0] = *(float4*)&Vs[(n + u) * 132 + tx * 8];
                *(float4*)&vv[u][4] = *(float4*)&Vs[(n + u) * 132 + tx * 8 + 4];
            }
#pragma unroll
            for (int u = 0; u < 4; ++u)
#pragma unroll
                for (int i = 0; i < 4; ++i)
#pragma unroll
                    for (int c = 0; c < 8; ++c)
                        o[i][c] = fmaf(pv[i][u], vv[u][c], o[i][c]);
        }
    }

#pragma unroll
    for (int i = 0; i < 4; ++i) {
        float inv = 1.f / l_i[i];
        int trow = m0 + ty * 4 + i;
        float* op = &O[((size_t)(b * T_ + trow)) * TOT_ + h * HD_ + tx * 8];
        *(float4*)&op[0] = make_float4(o[i][0] * inv, o[i][1] * inv, o[i][2] * inv, o[i][3] * inv);
        *(float4*)&op[4] = make_float4(o[i][4] * inv, o[i][5] * inv, o[i][6] * inv, o[i][7] * inv);
    }
}

// ---------------- launch ----------------
extern "C" void kernel_launch(void* const* d_in, const int* in_sizes, int n_in,
                              void* d_out, int out_size) {
    const float* x   = (const float*)d_in[0];
    const float* cs  = (const float*)d_in[1];
    const float* sn  = (const float*)d_in[2];
    const float* Wq  = (const float*)d_in[3];
    const float* Wk  = (const float*)d_in[4];
    const float* Wv  = (const float*)d_in[5];
    const float* Wo  = (const float*)d_in[6];
    float* out = (float*)d_out;

    float *qkv, *Qh, *Kh, *Vh, *Og;
    __nv_bfloat16 *xh, *xl, *wqh, *wql, *woh, *wol, *oh, *ol;
    cudaGetSymbolAddress((void**)&qkv, g_qkv);
    cudaGetSymbolAddress((void**)&Qh, g_Q);
    cudaGetSymbolAddress((void**)&Kh, g_K);
    cudaGetSymbolAddress((void**)&Vh, g_V);
    cudaGetSymbolAddress((void**)&Og, g_O);
    cudaGetSymbolAddress((void**)&xh, g_xh);
    cudaGetSymbolAddress((void**)&xl, g_xl);
    cudaGetSymbolAddress((void**)&wqh, g_wqh);
    cudaGetSymbolAddress((void**)&wql, g_wql);
    cudaGetSymbolAddress((void**)&woh, g_woh);
    cudaGetSymbolAddress((void**)&wol, g_wol);
    cudaGetSymbolAddress((void**)&oh, g_oh);
    cudaGetSymbolAddress((void**)&ol, g_ol);

    cudaFuncSetAttribute(gemm_bf16x3, cudaFuncAttributeMaxDynamicSharedMemorySize, GEMM_SMEM);
    cudaFuncSetAttribute(flash_attn, cudaFuncAttributeMaxDynamicSharedMemorySize, FA_SMEM);

    // split inputs
    split_f32<<<(MROWS * DM_ / 4 + 255) / 256, 256>>>(x, xh, xl, MROWS * DM_ / 4);
    split_wqkv<<<(DM_ * NQKV / 4 + 255) / 256, 256>>>(Wq, Wk, Wv, wqh, wql);
    split_f32<<<(TOT_ * DM_ / 4 + 255) / 256, 256>>>(Wo, woh, wol, TOT_ * DM_ / 4);

    // fused QKV projection: [4096,2048] @ [2048,6144]
    dim3 qkvGrid(NQKV / 128, MROWS / 128);   // (48, 32)
    gemm_bf16x3<<<qkvGrid, 256, GEMM_SMEM>>>(xh, xl, wqh, wql, qkv, NQKV);

    int writeKV = (out_size >= 3 * MAIN_ELEMS) ? 1 : 0;
    float* outK = out + MAIN_ELEMS;
    float* outV = out + 2 * MAIN_ELEMS;
    int ropeThreads = B_ * T_ * H_ * 64;
    rope_permute<<<ropeThreads / 256, 256>>>(qkv, cs, sn, Qh, Kh, Vh,
                                             writeKV ? outK : Qh,
                                             writeKV ? outV : Qh, writeKV);

    dim3 faGrid(T_ / 64, B_ * H_);
    flash_attn<<<faGrid, 256, FA_SMEM>>>(Qh, Kh, Vh, Og);

    // split attention output, final projection
    split_f32<<<(MROWS * TOT_ / 4 + 255) / 256, 256>>>(Og, oh, ol, MROWS * TOT_ / 4);
    dim3 oGrid(DM_ / 128, MROWS / 128);      // (16, 32)
    gemm_bf16x3<<<oGrid, 256, GEMM_SMEM>>>(oh, ol, woh, wol, out, DM_);
}

// round 4
// speedup vs baseline: 2.6134x; 1.6667x over previous
#include <cuda_runtime.h>
#include <cuda_bf16.h>
#include <math.h>

// Problem constants
#define B_  2
#define T_  2048
#define DM_ 2048
#define H_  16
#define HD_ 128
#define TOT_ 2048
#define MROWS 4096
#define NQKV 6144
#define MAIN_ELEMS (MROWS * DM_)

// ---------------- scratch ----------------
__device__ float g_qkv[MROWS * NQKV];        // fused QKV proj output [b*t][6144]
__device__ float g_O[MROWS * TOT_];          // attention out [b,t,h*hd]
__device__ __align__(16) __nv_bfloat16 g_xh[MROWS * DM_],  g_xl[MROWS * DM_];
__device__ __align__(16) __nv_bfloat16 g_wqh[DM_ * NQKV],  g_wql[DM_ * NQKV];
__device__ __align__(16) __nv_bfloat16 g_woh[TOT_ * DM_],  g_wol[TOT_ * DM_];
__device__ __align__(16) __nv_bfloat16 g_oh[MROWS * TOT_], g_ol[MROWS * TOT_];
// bf16 hi/lo Q/K/V in [b,h,t,hd]
__device__ __align__(16) __nv_bfloat16 g_Qhh[MROWS * TOT_], g_Qll[MROWS * TOT_];
__device__ __align__(16) __nv_bfloat16 g_Khh[MROWS * TOT_], g_Kll[MROWS * TOT_];
__device__ __align__(16) __nv_bfloat16 g_Vhh[MROWS * TOT_], g_Vll[MROWS * TOT_];

// ---------------- split fp32 -> (hi, lo) bf16 ----------------
__device__ __forceinline__ void split1(float v, unsigned short& h, unsigned short& l) {
    __nv_bfloat16 hb = __float2bfloat16(v);
    __nv_bfloat16 lb = __float2bfloat16(v - __bfloat162float(hb));
    h = __bfloat16_as_ushort(hb);
    l = __bfloat16_as_ushort(lb);
}

__global__ __launch_bounds__(256) void split_f32(const float* __restrict__ src,
                                                 __nv_bfloat16* __restrict__ hi,
                                                 __nv_bfloat16* __restrict__ lo, int n4) {
    int i = blockIdx.x * blockDim.x + threadIdx.x;
    if (i >= n4) return;
    float4 v = ((const float4*)src)[i];
    unsigned short h0,h1,h2,h3,l0,l1,l2,l3;
    split1(v.x,h0,l0); split1(v.y,h1,l1); split1(v.z,h2,l2); split1(v.w,h3,l3);
    uint2 uh, ul;
    uh.x = (unsigned)h0 | ((unsigned)h1 << 16); uh.y = (unsigned)h2 | ((unsigned)h3 << 16);
    ul.x = (unsigned)l0 | ((unsigned)l1 << 16); ul.y = (unsigned)l2 | ((unsigned)l3 << 16);
    ((uint2*)hi)[i] = uh;
    ((uint2*)lo)[i] = ul;
}

__global__ __launch_bounds__(256) void split_wqkv(const float* __restrict__ Wq,
                                                  const float* __restrict__ Wk,
                                                  const float* __restrict__ Wv,
                                                  __nv_bfloat16* __restrict__ hi,
                                                  __nv_bfloat16* __restrict__ lo) {
    int i = blockIdx.x * blockDim.x + threadIdx.x;
    if (i >= DM_ * NQKV / 4) return;
    int k = i / (NQKV / 4);
    int n = (i % (NQKV / 4)) * 4;
    const float* src;
    int nn;
    if (n < 2048)       { src = Wq; nn = n; }
    else if (n < 4096)  { src = Wk; nn = n - 2048; }
    else                { src = Wv; nn = n - 4096; }
    float4 v = *(const float4*)&src[(size_t)k * 2048 + nn];
    unsigned short h0,h1,h2,h3,l0,l1,l2,l3;
    split1(v.x,h0,l0); split1(v.y,h1,l1); split1(v.z,h2,l2); split1(v.w,h3,l3);
    uint2 uh, ul;
    uh.x = (unsigned)h0 | ((unsigned)h1 << 16); uh.y = (unsigned)h2 | ((unsigned)h3 << 16);
    ul.x = (unsigned)l0 | ((unsigned)l1 << 16); ul.y = (unsigned)l2 | ((unsigned)l3 << 16);
    ((uint2*)hi)[i] = uh;
    ((uint2*)lo)[i] = ul;
}

// ---------------- MMA helpers ----------------
__device__ __forceinline__ void ldsm_x4(unsigned& r0, unsigned& r1, unsigned& r2, unsigned& r3,
                                        unsigned addr) {
    asm volatile("ldmatrix.sync.aligned.m8n8.x4.shared.b16 {%0,%1,%2,%3}, [%4];\n"
                 : "=r"(r0), "=r"(r1), "=r"(r2), "=r"(r3) : "r"(addr));
}
__device__ __forceinline__ void ldsm_x4t(unsigned& r0, unsigned& r1, unsigned& r2, unsigned& r3,
                                         unsigned addr) {
    asm volatile("ldmatrix.sync.aligned.m8n8.x4.trans.shared.b16 {%0,%1,%2,%3}, [%4];\n"
                 : "=r"(r0), "=r"(r1), "=r"(r2), "=r"(r3) : "r"(addr));
}
__device__ __forceinline__ void mma16816(float* c, const unsigned* a, const unsigned* b) {
    asm volatile("mma.sync.aligned.m16n8k16.row.col.f32.bf16.bf16.f32 "
                 "{%0,%1,%2,%3}, {%4,%5,%6,%7}, {%8,%9}, {%0,%1,%2,%3};\n"
                 : "+f"(c[0]), "+f"(c[1]), "+f"(c[2]), "+f"(c[3])
                 : "r"(a[0]), "r"(a[1]), "r"(a[2]), "r"(a[3]), "r"(b[0]), "r"(b[1]));
}
__device__ __forceinline__ unsigned packbf2(float x, float y) {
    __nv_bfloat162 h2 = __floats2bfloat162_rn(x, y);
    return *(unsigned*)&h2;
}

// ---------------- BF16x3 tensor-core GEMM (unchanged from R3 pass) ----------------
#define GK 2048
#define LDA 40
#define LDB 136
#define STG_AH 0
#define STG_AL 5120
#define STG_BH 10240
#define STG_BL 14592
#define STG_SZ 18944
#define GEMM_SMEM (2 * STG_SZ * 2)

__global__ __launch_bounds__(256) void gemm_bf16x3(const __nv_bfloat16* __restrict__ Ah,
                                                   const __nv_bfloat16* __restrict__ Al,
                                                   const __nv_bfloat16* __restrict__ Bh,
                                                   const __nv_bfloat16* __restrict__ Bl,
                                                   float* __restrict__ C, int N) {
    extern __shared__ __nv_bfloat16 sm[];
    const int tid = threadIdx.x;
    const int lane = tid & 31, wid = tid >> 5;
    const int wm = wid & 3, wn = wid >> 2;
    const int m0 = blockIdx.y * 128, n0 = blockIdx.x * 128;

    uint4 ra_h[2], ra_l[2], rb_h[2], rb_l[2];
    int ar[2], ac[2], br[2], bc[2];
#pragma unroll
    for (int q = 0; q < 2; ++q) {
        int c = tid * 2 + q;
        ar[q] = c >> 2;  ac[q] = (c & 3) << 3;
        br[q] = c >> 4;  bc[q] = (c & 15) << 3;
    }

    float acc[2][8][4];
#pragma unroll
    for (int mt = 0; mt < 2; ++mt)
#pragma unroll
        for (int nt = 0; nt < 8; ++nt)
#pragma unroll
            for (int e = 0; e < 4; ++e) acc[mt][nt][e] = 0.f;

    auto load_regs = [&](int k0) {
#pragma unroll
        for (int q = 0; q < 2; ++q) {
            size_t aoff = (size_t)(m0 + ar[q]) * GK + k0 + ac[q];
            size_t boff = (size_t)(k0 + br[q]) * N + n0 + bc[q];
            ra_h[q] = *(const uint4*)(Ah + aoff);
            ra_l[q] = *(const uint4*)(Al + aoff);
            rb_h[q] = *(const uint4*)(Bh + boff);
            rb_l[q] = *(const uint4*)(Bl + boff);
        }
    };
    auto store_stage = [&](int s) {
        __nv_bfloat16* base = sm + s * STG_SZ;
#pragma unroll
        for (int q = 0; q < 2; ++q) {
            int ao = ar[q] * LDA + ac[q];
            int bo = br[q] * LDB + bc[q];
            *(uint4*)(base + STG_AH + ao) = ra_h[q];
            *(uint4*)(base + STG_AL + ao) = ra_l[q];
            *(uint4*)(base + STG_BH + bo) = rb_h[q];
            *(uint4*)(base + STG_BL + bo) = rb_l[q];
        }
    };

    load_regs(0);
    store_stage(0);
    __syncthreads();

    const int lrow = lane & 15;
    const int lcol = (lane >> 4) << 3;

    for (int it = 0; it < GK / 32; ++it) {
        if (it < GK / 32 - 1) load_regs((it + 1) * 32);

        const __nv_bfloat16* base = sm + (it & 1) * STG_SZ;
        unsigned s_ah = (unsigned)__cvta_generic_to_shared(base + STG_AH);
        unsigned s_al = (unsigned)__cvta_generic_to_shared(base + STG_AL);
        unsigned s_bh = (unsigned)__cvta_generic_to_shared(base + STG_BH);
        unsigned s_bl = (unsigned)__cvta_generic_to_shared(base + STG_BL);

#pragma unroll
        for (int ks = 0; ks < 32; ks += 16) {
            unsigned a_h[2][4], a_l[2][4];
#pragma unroll
            for (int mt = 0; mt < 2; ++mt) {
                unsigned off = ((wm * 32 + mt * 16 + lrow) * LDA + ks + lcol) * 2;
                ldsm_x4(a_h[mt][0], a_h[mt][1], a_h[mt][2], a_h[mt][3], s_ah + off);
                ldsm_x4(a_l[mt][0], a_l[mt][1], a_l[mt][2], a_l[mt][3], s_al + off);
            }
            unsigned b_h[8][2], b_l[8][2];
#pragma unroll
            for (int nt2 = 0; nt2 < 4; ++nt2) {
                unsigned off = ((ks + lrow) * LDB + wn * 64 + nt2 * 16 + lcol) * 2;
                unsigned t0, t1, t2, t3;
                ldsm_x4t(t0, t1, t2, t3, s_bh + off);
                b_h[2*nt2][0] = t0; b_h[2*nt2][1] = t1;
                b_h[2*nt2+1][0] = t2; b_h[2*nt2+1][1] = t3;
                ldsm_x4t(t0, t1, t2, t3, s_bl + off);
                b_l[2*nt2][0] = t0; b_l[2*nt2][1] = t1;
                b_l[2*nt2+1][0] = t2; b_l[2*nt2+1][1] = t3;
            }
#pragma unroll
            for (int mt = 0; mt < 2; ++mt)
#pragma unroll
                for (int nt = 0; nt < 8; ++nt) {
                    mma16816(acc[mt][nt], a_h[mt], b_h[nt]);
                    mma16816(acc[mt][nt], a_h[mt], b_l[nt]);
                    mma16816(acc[mt][nt], a_l[mt], b_h[nt]);
                }
        }
        if (it < GK / 32 - 1) store_stage((it + 1) & 1);
        __syncthreads();
    }

    const int erow = lane >> 2;
    const int ecol = (lane & 3) << 1;
#pragma unroll
    for (int mt = 0; mt < 2; ++mt)
#pragma unroll
        for (int nt = 0; nt < 8; ++nt) {
            int gr = m0 + wm * 32 + mt * 16 + erow;
            int gc = n0 + wn * 64 + nt * 8 + ecol;
            *(float2*)&C[(size_t)gr * N + gc]       = make_float2(acc[mt][nt][0], acc[mt][nt][1]);
            *(float2*)&C[(size_t)(gr + 8) * N + gc] = make_float2(acc[mt][nt][2], acc[mt][nt][3]);
        }
}

// ---------------- RoPE + permute + bf16 hi/lo split ----------------
// Q is pre-scaled by HD^-0.5 so attention scores need no extra scale.
__device__ __forceinline__ void split_store(float v, __nv_bfloat16* ph, __nv_bfloat16* pl) {
    __nv_bfloat16 hb = __float2bfloat16(v);
    *ph = hb;
    *pl = __float2bfloat16(v - __bfloat162float(hb));
}

__global__ __launch_bounds__(256) void rope_split(const float* __restrict__ qkv,
                                                  const float* __restrict__ cosp,
                                                  const float* __restrict__ sinp,
                                                  __nv_bfloat16* __restrict__ Qh, __nv_bfloat16* __restrict__ Ql,
                                                  __nv_bfloat16* __restrict__ Kh, __nv_bfloat16* __restrict__ Kl,
                                                  __nv_bfloat16* __restrict__ Vh, __nv_bfloat16* __restrict__ Vl,
                                                  float* __restrict__ outK,
                                                  float* __restrict__ outV,
                                                  int writeKV) {
    int idx = blockIdx.x * blockDim.x + threadIdx.x;
    int d = idx & 63;
    int h = (idx >> 6) & 15;
    int t = (idx >> 10) & 2047;
    int b = idx >> 21;

    const float scale = 0.08838834764831843f;   // 128^-0.5
    size_t in0 = ((size_t)(b * T_ + t)) * NQKV + h * HD_;
    size_t ob  = (((size_t)(b * H_ + h)) * T_ + t) * HD_;

    float c1 = cosp[t * HD_ + d],      s1 = sinp[t * HD_ + d];
    float c2 = cosp[t * HD_ + d + 64], s2 = sinp[t * HD_ + d + 64];

    float q1 = qkv[in0 + d], q2 = qkv[in0 + d + 64];
    float qo1 = (q1 * c1 - q2 * s1) * scale;
    float qo2 = (q2 * c2 + q1 * s2) * scale;
    split_store(qo1, Qh + ob + d, Ql + ob + d);
    split_store(qo2, Qh + ob + d + 64, Ql + ob + d + 64);

    float k1 = qkv[in0 + 2048 + d], k2 = qkv[in0 + 2048 + d + 64];
    float ko1 = k1 * c1 - k2 * s1;
    float ko2 = k2 * c2 + k1 * s2;
    split_store(ko1, Kh + ob + d, Kl + ob + d);
    split_store(ko2, Kh + ob + d + 64, Kl + ob + d + 64);

    float v1 = qkv[in0 + 4096 + d], v2 = qkv[in0 + 4096 + d + 64];
    split_store(v1, Vh + ob + d, Vl + ob + d);
    split_store(v2, Vh + ob + d + 64, Vl + ob + d + 64);

    if (writeKV) {
        outK[ob + d] = ko1; outK[ob + d + 64] = ko2;
        outV[ob + d] = v1;  outV[ob + d + 64] = v2;
    }
}

// ---------------- Tensor-core flash attention (bf16x3), causal ----------------
// BM=BN=64, 128 threads (4 warps). Warp w owns query rows [w*16, w*16+16).
#define FA_LD 136
#define FA_SMEM (6 * 64 * FA_LD * 2)    // 104448 B

__global__ __launch_bounds__(128, 2) void flash_attn_tc(
        const __nv_bfloat16* __restrict__ Qh_, const __nv_bfloat16* __restrict__ Ql_,
        const __nv_bfloat16* __restrict__ Kh_, const __nv_bfloat16* __restrict__ Kl_,
        const __nv_bfloat16* __restrict__ Vh_, const __nv_bfloat16* __restrict__ Vl_,
        float* __restrict__ O) {
    const int qt = blockIdx.x;
    const int bh = blockIdx.y;
    const int b = bh >> 4, h = bh & 15;
    const int m0 = qt * 64;
    const size_t base = (size_t)bh * T_ * HD_;

    extern __shared__ __nv_bfloat16 sb[];
    __nv_bfloat16* sQh = sb;
    __nv_bfloat16* sQl = sQh + 64 * FA_LD;
    __nv_bfloat16* sKh = sQl + 64 * FA_LD;
    __nv_bfloat16* sKl = sKh + 64 * FA_LD;
    __nv_bfloat16* sVh = sKl + 64 * FA_LD;
    __nv_bfloat16* sVl = sVh + 64 * FA_LD;

    const int tid = threadIdx.x;
    const int lane = tid & 31, w = tid >> 5;
    const int g = lane >> 2, t4 = lane & 3;
    const int l8 = lane & 7, sel = lane >> 3;
    // ldmatrix per-lane tile-local offsets
    const int aro = l8 + ((sel & 1) ? 8 : 0), aco = (sel & 2) ? 8 : 0;   // A (Q / row-major m x k)
    const int bro = l8 + ((sel & 2) ? 8 : 0), bco = (sel & 1) ? 8 : 0;   // B (K, n x k row-major)
    const int vro = l8 + ((sel & 1) ? 8 : 0), vco = (sel & 2) ? 8 : 0;   // V (trans, k x n row-major)

    // load Q tile (hi/lo)
    for (int i = tid; i < 64 * 16; i += 128) {
        int r = i >> 4, c = (i & 15) * 8;
        size_t goff = base + (size_t)(m0 + r) * HD_ + c;
        *(uint4*)&sQh[r * FA_LD + c] = *(const uint4*)&Qh_[goff];
        *(uint4*)&sQl[r * FA_LD + c] = *(const uint4*)&Ql_[goff];
    }

    unsigned uQh = (unsigned)__cvta_generic_to_shared(sQh);
    unsigned uQl = (unsigned)__cvta_generic_to_shared(sQl);
    unsigned uKh = (unsigned)__cvta_generic_to_shared(sKh);
    unsigned uKl = (unsigned)__cvta_generic_to_shared(sKl);
    unsigned uVh = (unsigned)__cvta_generic_to_shared(sVh);
    unsigned uVl = (unsigned)__cvta_generic_to_shared(sVl);

    float o[16][4];
#pragma unroll
    for (int i = 0; i < 16; ++i)
#pragma unroll
        for (int e = 0; e < 4; ++e) o[i][e] = 0.f;
    float m_i[2] = {-1e30f, -1e30f};
    float l_i[2] = {0.f, 0.f};

    for (int tt = 0; tt <= qt; ++tt) {
        const int n0 = tt * 64;
        __syncthreads();
        for (int i = tid; i < 64 * 16; i += 128) {
            int r = i >> 4, c = (i & 15) * 8;
            size_t goff = base + (size_t)(n0 + r) * HD_ + c;
            *(uint4*)&sKh[r * FA_LD + c] = *(const uint4*)&Kh_[goff];
            *(uint4*)&sKl[r * FA_LD + c] = *(const uint4*)&Kl_[goff];
            *(uint4*)&sVh[r * FA_LD + c] = *(const uint4*)&Vh_[goff];
            *(uint4*)&sVl[r * FA_LD + c] = *(const uint4*)&Vl_[goff];
        }
        __syncthreads();

        // S = Q @ K^T   (16 x 64 per warp), bf16x3
        float s[8][4];
#pragma unroll
        for (int c = 0; c < 8; ++c)
#pragma unroll
            for (int e = 0; e < 4; ++e) s[c][e] = 0.f;

#pragma unroll
        for (int kk = 0; kk < 8; ++kk) {
            unsigned ah[4], al[4];
            unsigned qoff = (unsigned)(((w * 16 + aro) * FA_LD + kk * 16 + aco) * 2);
            ldsm_x4(ah[0], ah[1], ah[2], ah[3], uQh + qoff);
            ldsm_x4(al[0], al[1], al[2], al[3], uQl + qoff);
#pragma unroll
            for (int nc = 0; nc < 4; ++nc) {
                unsigned koff = (unsigned)(((nc * 16 + bro) * FA_LD + kk * 16 + bco) * 2);
                unsigned h0, h1, h2, h3, q0, q1, q2, q3;
                ldsm_x4(h0, h1, h2, h3, uKh + koff);
                ldsm_x4(q0, q1, q2, q3, uKl + koff);
                unsigned bh0[2] = {h0, h1}, bh1[2] = {h2, h3};
                unsigned bl0[2] = {q0, q1}, bl1[2] = {q2, q3};
                mma16816(s[2*nc],   ah, bh0);
                mma16816(s[2*nc],   ah, bl0);
                mma16816(s[2*nc],   al, bh0);
                mma16816(s[2*nc+1], ah, bh1);
                mma16816(s[2*nc+1], ah, bl1);
                mma16816(s[2*nc+1], al, bh1);
            }
        }

        // causal mask (only diagonal tile: tt == qt)
        if (tt == qt) {
            int r0 = m0 + w * 16 + g, r1 = r0 + 8;
#pragma unroll
            for (int c = 0; c < 8; ++c) {
                int col = n0 + c * 8 + 2 * t4;
                if (col     > r0) s[c][0] = -1e30f;
                if (col + 1 > r0) s[c][1] = -1e30f;
                if (col     > r1) s[c][2] = -1e30f;
                if (col + 1 > r1) s[c][3] = -1e30f;
            }
        }

        // online softmax (rows g and g+8)
        float mt0 = -1e30f, mt1 = -1e30f;
#pragma unroll
        for (int c = 0; c < 8; ++c) {
            mt0 = fmaxf(mt0, fmaxf(s[c][0], s[c][1]));
            mt1 = fmaxf(mt1, fmaxf(s[c][2], s[c][3]));
        }
        mt0 = fmaxf(mt0, __shfl_xor_sync(0xffffffffu, mt0, 1));
        mt0 = fmaxf(mt0, __shfl_xor_sync(0xffffffffu, mt0, 2));
        mt1 = fmaxf(mt1, __shfl_xor_sync(0xffffffffu, mt1, 1));
        mt1 = fmaxf(mt1, __shfl_xor_sync(0xffffffffu, mt1, 2));

        float mn0 = fmaxf(m_i[0], mt0), mn1 = fmaxf(m_i[1], mt1);
        float al0 = __expf(m_i[0] - mn0), al1 = __expf(m_i[1] - mn1);
        float sum0 = 0.f, sum1 = 0.f;
#pragma unroll
        for (int c = 0; c < 8; ++c) {
            s[c][0] = __expf(s[c][0] - mn0);
            s[c][1] = __expf(s[c][1] - mn0);
            s[c][2] = __expf(s[c][2] - mn1);
            s[c][3] = __expf(s[c][3] - mn1);
            sum0 += s[c][0] + s[c][1];
            sum1 += s[c][2] + s[c][3];
        }
        sum0 += __shfl_xor_sync(0xffffffffu, sum0, 1);
        sum0 += __shfl_xor_sync(0xffffffffu, sum0, 2);
        sum1 += __shfl_xor_sync(0xffffffffu, sum1, 1);
        sum1 += __shfl_xor_sync(0xffffffffu, sum1, 2);

        l_i[0] = l_i[0] * al0 + sum0;
        l_i[1] = l_i[1] * al1 + sum1;
        m_i[0] = mn0; m_i[1] = mn1;

#pragma unroll
        for (int i = 0; i < 16; ++i) {
            o[i][0] *= al0; o[i][1] *= al0;
            o[i][2] *= al1; o[i][3] *= al1;
        }

        // O += P @ V, P split hi/lo, V split hi/lo
#pragma unroll
        for (int j = 0; j < 4; ++j) {
            // build P A-fragments from s[2j], s[2j+1]
            unsigned aPh[4], aPl[4];
            float p00 = s[2*j][0],   p01 = s[2*j][1],   p02 = s[2*j][2],   p03 = s[2*j][3];
            float p10 = s[2*j+1][0], p11 = s[2*j+1][1], p12 = s[2*j+1][2], p13 = s[2*j+1][3];
            float h00 = __bfloat162float(__float2bfloat16(p00));
            float h01 = __bfloat162float(__float2bfloat16(p01));
            float h02 = __bfloat162float(__float2bfloat16(p02));
            float h03 = __bfloat162float(__float2bfloat16(p03));
            float h10 = __bfloat162float(__float2bfloat16(p10));
            float h11 = __bfloat162float(__float2bfloat16(p11));
            float h12 = __bfloat162float(__float2bfloat16(p12));
            float h13 = __bfloat162float(__float2bfloat16(p13));
            aPh[0] = packbf2(h00, h01);  aPh[1] = packbf2(h02, h03);
            aPh[2] = packbf2(h10, h11);  aPh[3] = packbf2(h12, h13);
            aPl[0] = packbf2(p00 - h00, p01 - h01);
            aPl[1] = packbf2(p02 - h02, p03 - h03);
            aPl[2] = packbf2(p10 - h10, p11 - h11);
            aPl[3] = packbf2(p12 - h12, p13 - h13);

#pragma unroll
            for (int dd = 0; dd < 8; ++dd) {
                unsigned voff = (unsigned)(((j * 16 + vro) * FA_LD + dd * 16 + vco) * 2);
                unsigned h0, h1, h2, h3, q0, q1, q2, q3;
                ldsm_x4t(h0, h1, h2, h3, uVh + voff);
                ldsm_x4t(q0, q1, q2, q3, uVl + voff);
                unsigned bh0[2] = {h0, h1}, bh1[2] = {h2, h3};
                unsigned bl0[2] = {q0, q1}, bl1[2] = {q2, q3};
                mma16816(o[2*dd],   aPh, bh0);
                mma16816(o[2*dd],   aPh, bl0);
                mma16816(o[2*dd],   aPl, bh0);
                mma16816(o[2*dd+1], aPh, bh1);
                mma16816(o[2*dd+1], aPh, bl1);
                mma16816(o[2*dd+1], aPl, bh1);
            }
        }
    }

    // epilogue: normalize and write to [b, t, h*HD]
    float inv0 = 1.f / l_i[0], inv1 = 1.f / l_i[1];
    int trow0 = m0 + w * 16 + g;
#pragma unroll
    for (int c = 0; c < 16; ++c) {
        int gc = h * HD_ + c * 8 + 2 * t4;
        *(float2*)&O[((size_t)(b * T_ + trow0)) * TOT_ + gc] =
            make_float2(o[c][0] * inv0, o[c][1] * inv0);
        *(float2*)&O[((size_t)(b * T_ + trow0 + 8)) * TOT_ + gc] =
            make_float2(o[c][2] * inv1, o[c][3] * inv1);
    }
}

// ---------------- launch ----------------
extern "C" void kernel_launch(void* const* d_in, const int* in_sizes, int n_in,
                              void* d_out, int out_size) {
    const float* x   = (const float*)d_in[0];
    const float* cs  = (const float*)d_in[1];
    const float* sn  = (const float*)d_in[2];
    const float* Wq  = (const float*)d_in[3];
    const float* Wk  = (const float*)d_in[4];
    const float* Wv  = (const float*)d_in[5];
    const float* Wo  = (const float*)d_in[6];
    float* out = (float*)d_out;

    float *qkv, *Og;
    __nv_bfloat16 *xh, *xl, *wqh, *wql, *woh, *wol, *oh, *ol;
    __nv_bfloat16 *Qh, *Ql, *Kh, *Kl, *Vh, *Vl;
    cudaGetSymbolAddress((void**)&qkv, g_qkv);
    cudaGetSymbolAddress((void**)&Og, g_O);
    cudaGetSymbolAddress((void**)&xh, g_xh);
    cudaGetSymbolAddress((void**)&xl, g_xl);
    cudaGetSymbolAddress((void**)&wqh, g_wqh);
    cudaGetSymbolAddress((void**)&wql, g_wql);
    cudaGetSymbolAddress((void**)&woh, g_woh);
    cudaGetSymbolAddress((void**)&wol, g_wol);
    cudaGetSymbolAddress((void**)&oh, g_oh);
    cudaGetSymbolAddress((void**)&ol, g_ol);
    cudaGetSymbolAddress((void**)&Qh, g_Qhh);
    cudaGetSymbolAddress((void**)&Ql, g_Qll);
    cudaGetSymbolAddress((void**)&Kh, g_Khh);
    cudaGetSymbolAddress((void**)&Kl, g_Kll);
    cudaGetSymbolAddress((void**)&Vh, g_Vhh);
    cudaGetSymbolAddress((void**)&Vl, g_Vll);

    cudaFuncSetAttribute(gemm_bf16x3, cudaFuncAttributeMaxDynamicSharedMemorySize, GEMM_SMEM);
    cudaFuncSetAttribute(flash_attn_tc, cudaFuncAttributeMaxDynamicSharedMemorySize, FA_SMEM);

    // split inputs
    split_f32<<<(MROWS * DM_ / 4 + 255) / 256, 256>>>(x, xh, xl, MROWS * DM_ / 4);
    split_wqkv<<<(DM_ * NQKV / 4 + 255) / 256, 256>>>(Wq, Wk, Wv, wqh, wql);
    split_f32<<<(TOT_ * DM_ / 4 + 255) / 256, 256>>>(Wo, woh, wol, TOT_ * DM_ / 4);

    // fused QKV projection: [4096,2048] @ [2048,6144]
    dim3 qkvGrid(NQKV / 128, MROWS / 128);
    gemm_bf16x3<<<qkvGrid, 256, GEMM_SMEM>>>(xh, xl, wqh, wql, qkv, NQKV);

    int writeKV = (out_size >= 3 * MAIN_ELEMS) ? 1 : 0;
    float* outK = out + MAIN_ELEMS;
    float* outV = out + 2 * MAIN_ELEMS;
    int ropeThreads = B_ * T_ * H_ * 64;
    rope_split<<<ropeThreads / 256, 256>>>(qkv, cs, sn, Qh, Ql, Kh, Kl, Vh, Vl,
                                           writeKV ? outK : Og,
                                           writeKV ? outV : Og, writeKV);

    dim3 faGrid(T_ / 64, B_ * H_);
    flash_attn_tc<<<faGrid, 128, FA_SMEM>>>(Qh, Ql, Kh, Kl, Vh, Vl, Og);

    // split attention output, final projection
    split_f32<<<(MROWS * TOT_ / 4 + 255) / 256, 256>>>(Og, oh, ol, MROWS * TOT_ / 4);
    dim3 oGrid(DM_ / 128, MROWS / 128);
    gemm_bf16x3<<<oGrid, 256, GEMM_SMEM>>>(oh, ol, woh, wol, out, DM_);
}

// round 5
// speedup vs baseline: 3.0542x; 1.1687x over previous
#include <cuda_runtime.h>
#include <cuda_bf16.h>
#include <math.h>

// Problem constants
#define B_  2
#define T_  2048
#define DM_ 2048
#define H_  16
#define HD_ 128
#define TOT_ 2048
#define MROWS 4096
#define NQKV 6144
#define MAIN_ELEMS (MROWS * DM_)

// ---------------- scratch ----------------
__device__ float g_qkv[MROWS * NQKV];
__device__ float g_O[MROWS * TOT_];
__device__ __align__(16) __nv_bfloat16 g_xh[MROWS * DM_],  g_xl[MROWS * DM_];
__device__ __align__(16) __nv_bfloat16 g_wqh[DM_ * NQKV],  g_wql[DM_ * NQKV];
__device__ __align__(16) __nv_bfloat16 g_woh[TOT_ * DM_],  g_wol[TOT_ * DM_];
__device__ __align__(16) __nv_bfloat16 g_oh[MROWS * TOT_], g_ol[MROWS * TOT_];
__device__ __align__(16) __nv_bfloat16 g_Qhh[MROWS * TOT_], g_Qll[MROWS * TOT_];
__device__ __align__(16) __nv_bfloat16 g_Khh[MROWS * TOT_], g_Kll[MROWS * TOT_];
__device__ __align__(16) __nv_bfloat16 g_Vhh[MROWS * TOT_], g_Vll[MROWS * TOT_];

// ---------------- split fp32 -> (hi, lo) bf16 ----------------
__device__ __forceinline__ void split1(float v, unsigned short& h, unsigned short& l) {
    __nv_bfloat16 hb = __float2bfloat16(v);
    __nv_bfloat16 lb = __float2bfloat16(v - __bfloat162float(hb));
    h = __bfloat16_as_ushort(hb);
    l = __bfloat16_as_ushort(lb);
}

__global__ __launch_bounds__(256) void split_f32(const float* __restrict__ src,
                                                 __nv_bfloat16* __restrict__ hi,
                                                 __nv_bfloat16* __restrict__ lo, int n4) {
    int i = blockIdx.x * blockDim.x + threadIdx.x;
    if (i >= n4) return;
    float4 v = ((const float4*)src)[i];
    unsigned short h0,h1,h2,h3,l0,l1,l2,l3;
    split1(v.x,h0,l0); split1(v.y,h1,l1); split1(v.z,h2,l2); split1(v.w,h3,l3);
    uint2 uh, ul;
    uh.x = (unsigned)h0 | ((unsigned)h1 << 16); uh.y = (unsigned)h2 | ((unsigned)h3 << 16);
    ul.x = (unsigned)l0 | ((unsigned)l1 << 16); ul.y = (unsigned)l2 | ((unsigned)l3 << 16);
    ((uint2*)hi)[i] = uh;
    ((uint2*)lo)[i] = ul;
}

__global__ __launch_bounds__(256) void split_wqkv(const float* __restrict__ Wq,
                                                  const float* __restrict__ Wk,
                                                  const float* __restrict__ Wv,
                                                  __nv_bfloat16* __restrict__ hi,
                                                  __nv_bfloat16* __restrict__ lo) {
    int i = blockIdx.x * blockDim.x + threadIdx.x;
    if (i >= DM_ * NQKV / 4) return;
    int k = i / (NQKV / 4);
    int n = (i % (NQKV / 4)) * 4;
    const float* src;
    int nn;
    if (n < 2048)       { src = Wq; nn = n; }
    else if (n < 4096)  { src = Wk; nn = n - 2048; }
    else                { src = Wv; nn = n - 4096; }
    float4 v = *(const float4*)&src[(size_t)k * 2048 + nn];
    unsigned short h0,h1,h2,h3,l0,l1,l2,l3;
    split1(v.x,h0,l0); split1(v.y,h1,l1); split1(v.z,h2,l2); split1(v.w,h3,l3);
    uint2 uh, ul;
    uh.x = (unsigned)h0 | ((unsigned)h1 << 16); uh.y = (unsigned)h2 | ((unsigned)h3 << 16);
    ul.x = (unsigned)l0 | ((unsigned)l1 << 16); ul.y = (unsigned)l2 | ((unsigned)l3 << 16);
    ((uint2*)hi)[i] = uh;
    ((uint2*)lo)[i] = ul;
}

// ---------------- MMA helpers ----------------
__device__ __forceinline__ void ldsm_x4(unsigned& r0, unsigned& r1, unsigned& r2, unsigned& r3,
                                        unsigned addr) {
    asm volatile("ldmatrix.sync.aligned.m8n8.x4.shared.b16 {%0,%1,%2,%3}, [%4];\n"
                 : "=r"(r0), "=r"(r1), "=r"(r2), "=r"(r3) : "r"(addr));
}
__device__ __forceinline__ void ldsm_x4t(unsigned& r0, unsigned& r1, unsigned& r2, unsigned& r3,
                                         unsigned addr) {
    asm volatile("ldmatrix.sync.aligned.m8n8.x4.trans.shared.b16 {%0,%1,%2,%3}, [%4];\n"
                 : "=r"(r0), "=r"(r1), "=r"(r2), "=r"(r3) : "r"(addr));
}
__device__ __forceinline__ void mma16816(float* c, const unsigned* a, const unsigned* b) {
    asm volatile("mma.sync.aligned.m16n8k16.row.col.f32.bf16.bf16.f32 "
                 "{%0,%1,%2,%3}, {%4,%5,%6,%7}, {%8,%9}, {%0,%1,%2,%3};\n"
                 : "+f"(c[0]), "+f"(c[1]), "+f"(c[2]), "+f"(c[3])
                 : "r"(a[0]), "r"(a[1]), "r"(a[2]), "r"(a[3]), "r"(b[0]), "r"(b[1]));
}
__device__ __forceinline__ unsigned packbf2(float x, float y) {
    __nv_bfloat162 h2 = __floats2bfloat162_rn(x, y);
    return *(unsigned*)&h2;
}
__device__ __forceinline__ void cp16(unsigned dst, const void* src) {
    asm volatile("cp.async.ca.shared.global [%0], [%1], 16;\n" :: "r"(dst), "l"(src));
}
__device__ __forceinline__ void cp_commit() {
    asm volatile("cp.async.commit_group;\n" ::: "memory");
}
template <int N>
__device__ __forceinline__ void cp_wait() {
    asm volatile("cp.async.wait_group %0;\n" :: "n"(N) : "memory");
}

// ---------------- BF16x3 tensor-core GEMM, cp.async double-buffered ----------------
#define GK 2048
#define LDA 40
#define LDB 136
#define STG_AH 0
#define STG_AL 5120
#define STG_BH 10240
#define STG_BL 14592
#define STG_SZ 18944
#define GEMM_SMEM (2 * STG_SZ * 2)   // 75776 B

__global__ __launch_bounds__(256, 2) void gemm_bf16x3(const __nv_bfloat16* __restrict__ Ah,
                                                      const __nv_bfloat16* __restrict__ Al,
                                                      const __nv_bfloat16* __restrict__ Bh,
                                                      const __nv_bfloat16* __restrict__ Bl,
                                                      float* __restrict__ C, int N) {
    extern __shared__ __nv_bfloat16 sm[];
    const unsigned smu = (unsigned)__cvta_generic_to_shared(sm);
    const int tid = threadIdx.x;
    const int lane = tid & 31, wid = tid >> 5;
    const int wm = wid & 3, wn = wid >> 2;
    const int m0 = blockIdx.y * 128, n0 = blockIdx.x * 128;

    int ar[2], ac[2], br[2], bc[2];
#pragma unroll
    for (int q = 0; q < 2; ++q) {
        int c = tid * 2 + q;
        ar[q] = c >> 2;  ac[q] = (c & 3) << 3;
        br[q] = c >> 4;  bc[q] = (c & 15) << 3;
    }

    float acc[2][8][4];
#pragma unroll
    for (int mt = 0; mt < 2; ++mt)
#pragma unroll
        for (int nt = 0; nt < 8; ++nt)
#pragma unroll
            for (int e = 0; e < 4; ++e) acc[mt][nt][e] = 0.f;

    auto prefetch = [&](int s, int k0) {
        unsigned sb = smu + (unsigned)(s * STG_SZ * 2);
#pragma unroll
        for (int q = 0; q < 2; ++q) {
            size_t aoff = (size_t)(m0 + ar[q]) * GK + k0 + ac[q];
            size_t boff = (size_t)(k0 + br[q]) * N + n0 + bc[q];
            unsigned ao = (unsigned)((STG_AH + ar[q] * LDA + ac[q]) * 2);
            unsigned bo = (unsigned)((STG_BH + br[q] * LDB + bc[q]) * 2);
            cp16(sb + ao, Ah + aoff);
            cp16(sb + ao + STG_AL * 2 - STG_AH * 2, Al + aoff);
            cp16(sb + bo, Bh + boff);
            cp16(sb + bo + (STG_BL - STG_BH) * 2, Bl + boff);
        }
    };

    prefetch(0, 0);
    cp_commit();
    cp_wait<0>();
    __syncthreads();

    const int lrow = lane & 15;
    const int lcol = (lane >> 4) << 3;
    const int NIT = GK / 32;

    for (int it = 0; it < NIT; ++it) {
        if (it + 1 < NIT) {
            prefetch((it + 1) & 1, (it + 1) * 32);
            cp_commit();
        }

        unsigned sb = smu + (unsigned)((it & 1) * STG_SZ * 2);
        unsigned s_ah = sb + STG_AH * 2;
        unsigned s_al = sb + STG_AL * 2;
        unsigned s_bh = sb + STG_BH * 2;
        unsigned s_bl = sb + STG_BL * 2;

#pragma unroll
        for (int ks = 0; ks < 32; ks += 16) {
            unsigned a_h[2][4], a_l[2][4];
#pragma unroll
            for (int mt = 0; mt < 2; ++mt) {
                unsigned off = ((wm * 32 + mt * 16 + lrow) * LDA + ks + lcol) * 2;
                ldsm_x4(a_h[mt][0], a_h[mt][1], a_h[mt][2], a_h[mt][3], s_ah + off);
                ldsm_x4(a_l[mt][0], a_l[mt][1], a_l[mt][2], a_l[mt][3], s_al + off);
            }
#pragma unroll
            for (int nt2 = 0; nt2 < 4; ++nt2) {
                unsigned off = ((ks + lrow) * LDB + wn * 64 + nt2 * 16 + lcol) * 2;
                unsigned h0, h1, h2, h3, q0, q1, q2, q3;
                ldsm_x4t(h0, h1, h2, h3, s_bh + off);
                ldsm_x4t(q0, q1, q2, q3, s_bl + off);
                unsigned bh0[2] = {h0, h1}, bh1[2] = {h2, h3};
                unsigned bl0[2] = {q0, q1}, bl1[2] = {q2, q3};
#pragma unroll
                for (int mt = 0; mt < 2; ++mt) {
                    mma16816(acc[mt][2*nt2],   a_h[mt], bh0);
                    mma16816(acc[mt][2*nt2],   a_h[mt], bl0);
                    mma16816(acc[mt][2*nt2],   a_l[mt], bh0);
                    mma16816(acc[mt][2*nt2+1], a_h[mt], bh1);
                    mma16816(acc[mt][2*nt2+1], a_h[mt], bl1);
                    mma16816(acc[mt][2*nt2+1], a_l[mt], bh1);
                }
            }
        }
        if (it + 1 < NIT) cp_wait<0>();
        __syncthreads();
    }

    const int erow = lane >> 2;
    const int ecol = (lane & 3) << 1;
#pragma unroll
    for (int mt = 0; mt < 2; ++mt)
#pragma unroll
        for (int nt = 0; nt < 8; ++nt) {
            int gr = m0 + wm * 32 + mt * 16 + erow;
            int gc = n0 + wn * 64 + nt * 8 + ecol;
            *(float2*)&C[(size_t)gr * N + gc]       = make_float2(acc[mt][nt][0], acc[mt][nt][1]);
            *(float2*)&C[(size_t)(gr + 8) * N + gc] = make_float2(acc[mt][nt][2], acc[mt][nt][3]);
        }
}

// ---------------- RoPE + permute + bf16 hi/lo split ----------------
__device__ __forceinline__ void split_store(float v, __nv_bfloat16* ph, __nv_bfloat16* pl) {
    __nv_bfloat16 hb = __float2bfloat16(v);
    *ph = hb;
    *pl = __float2bfloat16(v - __bfloat162float(hb));
}

__global__ __launch_bounds__(256) void rope_split(const float* __restrict__ qkv,
                                                  const float* __restrict__ cosp,
                                                  const float* __restrict__ sinp,
                                                  __nv_bfloat16* __restrict__ Qh, __nv_bfloat16* __restrict__ Ql,
                                                  __nv_bfloat16* __restrict__ Kh, __nv_bfloat16* __restrict__ Kl,
                                                  __nv_bfloat16* __restrict__ Vh, __nv_bfloat16* __restrict__ Vl,
                                                  float* __restrict__ outK,
                                                  float* __restrict__ outV,
                                                  int writeKV) {
    int idx = blockIdx.x * blockDim.x + threadIdx.x;
    int d = idx & 63;
    int h = (idx >> 6) & 15;
    int t = (idx >> 10) & 2047;
    int b = idx >> 21;

    const float scale = 0.08838834764831843f;
    size_t in0 = ((size_t)(b * T_ + t)) * NQKV + h * HD_;
    size_t ob  = (((size_t)(b * H_ + h)) * T_ + t) * HD_;

    float c1 = cosp[t * HD_ + d],      s1 = sinp[t * HD_ + d];
    float c2 = cosp[t * HD_ + d + 64], s2 = sinp[t * HD_ + d + 64];

    float q1 = qkv[in0 + d], q2 = qkv[in0 + d + 64];
    float qo1 = (q1 * c1 - q2 * s1) * scale;
    float qo2 = (q2 * c2 + q1 * s2) * scale;
    split_store(qo1, Qh + ob + d, Ql + ob + d);
    split_store(qo2, Qh + ob + d + 64, Ql + ob + d + 64);

    float k1 = qkv[in0 + 2048 + d], k2 = qkv[in0 + 2048 + d + 64];
    float ko1 = k1 * c1 - k2 * s1;
    float ko2 = k2 * c2 + k1 * s2;
    split_store(ko1, Kh + ob + d, Kl + ob + d);
    split_store(ko2, Kh + ob + d + 64, Kl + ob + d + 64);

    float v1 = qkv[in0 + 4096 + d], v2 = qkv[in0 + 4096 + d + 64];
    split_store(v1, Vh + ob + d, Vl + ob + d);
    split_store(v2, Vh + ob + d + 64, Vl + ob + d + 64);

    if (writeKV) {
        outK[ob + d] = ko1; outK[ob + d + 64] = ko2;
        outV[ob + d] = v1;  outV[ob + d + 64] = v2;
    }
}

// ---------------- Tensor-core flash attention (bf16x3), causal ----------------
#define FA_LD 136
#define FA_SMEM (6 * 64 * FA_LD * 2)

__global__ __launch_bounds__(128, 2) void flash_attn_tc(
        const __nv_bfloat16* __restrict__ Qh_, const __nv_bfloat16* __restrict__ Ql_,
        const __nv_bfloat16* __restrict__ Kh_, const __nv_bfloat16* __restrict__ Kl_,
        const __nv_bfloat16* __restrict__ Vh_, const __nv_bfloat16* __restrict__ Vl_,
        float* __restrict__ O) {
    const int qt = blockIdx.x;
    const int bh = blockIdx.y;
    const int b = bh >> 4, h = bh & 15;
    const int m0 = qt * 64;
    const size_t base = (size_t)bh * T_ * HD_;

    extern __shared__ __nv_bfloat16 sb[];
    __nv_bfloat16* sQh = sb;
    __nv_bfloat16* sQl = sQh + 64 * FA_LD;
    __nv_bfloat16* sKh = sQl + 64 * FA_LD;
    __nv_bfloat16* sKl = sKh + 64 * FA_LD;
    __nv_bfloat16* sVh = sKl + 64 * FA_LD;
    __nv_bfloat16* sVl = sVh + 64 * FA_LD;

    const int tid = threadIdx.x;
    const int lane = tid & 31, w = tid >> 5;
    const int g = lane >> 2, t4 = lane & 3;
    const int l8 = lane & 7, sel = lane >> 3;
    const int aro = l8 + ((sel & 1) ? 8 : 0), aco = (sel & 2) ? 8 : 0;
    const int bro = l8 + ((sel & 2) ? 8 : 0), bco = (sel & 1) ? 8 : 0;
    const int vro = l8 + ((sel & 1) ? 8 : 0), vco = (sel & 2) ? 8 : 0;

    for (int i = tid; i < 64 * 16; i += 128) {
        int r = i >> 4, c = (i & 15) * 8;
        size_t goff = base + (size_t)(m0 + r) * HD_ + c;
        *(uint4*)&sQh[r * FA_LD + c] = *(const uint4*)&Qh_[goff];
        *(uint4*)&sQl[r * FA_LD + c] = *(const uint4*)&Ql_[goff];
    }

    unsigned uQh = (unsigned)__cvta_generic_to_shared(sQh);
    unsigned uQl = (unsigned)__cvta_generic_to_shared(sQl);
    unsigned uKh = (unsigned)__cvta_generic_to_shared(sKh);
    unsigned uKl = (unsigned)__cvta_generic_to_shared(sKl);
    unsigned uVh = (unsigned)__cvta_generic_to_shared(sVh);
    unsigned uVl = (unsigned)__cvta_generic_to_shared(sVl);

    float o[16][4];
#pragma unroll
    for (int i = 0; i < 16; ++i)
#pragma unroll
        for (int e = 0; e < 4; ++e) o[i][e] = 0.f;
    float m_i[2] = {-1e30f, -1e30f};
    float l_i[2] = {0.f, 0.f};

    for (int tt = 0; tt <= qt; ++tt) {
        const int n0 = tt * 64;
        __syncthreads();
        for (int i = tid; i < 64 * 16; i += 128) {
            int r = i >> 4, c = (i & 15) * 8;
            size_t goff = base + (size_t)(n0 + r) * HD_ + c;
            *(uint4*)&sKh[r * FA_LD + c] = *(const uint4*)&Kh_[goff];
            *(uint4*)&sKl[r * FA_LD + c] = *(const uint4*)&Kl_[goff];
            *(uint4*)&sVh[r * FA_LD + c] = *(const uint4*)&Vh_[goff];
            *(uint4*)&sVl[r * FA_LD + c] = *(const uint4*)&Vl_[goff];
        }
        __syncthreads();

        float s[8][4];
#pragma unroll
        for (int c = 0; c < 8; ++c)
#pragma unroll
            for (int e = 0; e < 4; ++e) s[c][e] = 0.f;

#pragma unroll
        for (int kk = 0; kk < 8; ++kk) {
            unsigned ah[4], al[4];
            unsigned qoff = (unsigned)(((w * 16 + aro) * FA_LD + kk * 16 + aco) * 2);
            ldsm_x4(ah[0], ah[1], ah[2], ah[3], uQh + qoff);
            ldsm_x4(al[0], al[1], al[2], al[3], uQl + qoff);
#pragma unroll
            for (int nc = 0; nc < 4; ++nc) {
                unsigned koff = (unsigned)(((nc * 16 + bro) * FA_LD + kk * 16 + bco) * 2);
                unsigned h0, h1, h2, h3, q0, q1, q2, q3;
                ldsm_x4(h0, h1, h2, h3, uKh + koff);
                ldsm_x4(q0, q1, q2, q3, uKl + koff);
                unsigned bh0[2] = {h0, h1}, bh1[2] = {h2, h3};
                unsigned bl0[2] = {q0, q1}, bl1[2] = {q2, q3};
                mma16816(s[2*nc],   ah, bh0);
                mma16816(s[2*nc],   ah, bl0);
                mma16816(s[2*nc],   al, bh0);
                mma16816(s[2*nc+1], ah, bh1);
                mma16816(s[2*nc+1], ah, bl1);
                mma16816(s[2*nc+1], al, bh1);
            }
        }

        if (tt == qt) {
            int r0 = m0 + w * 16 + g, r1 = r0 + 8;
#pragma unroll
            for (int c = 0; c < 8; ++c) {
                int col = n0 + c * 8 + 2 * t4;
                if (col     > r0) s[c][0] = -1e30f;
                if (col + 1 > r0) s[c][1] = -1e30f;
                if (col     > r1) s[c][2] = -1e30f;
                if (col + 1 > r1) s[c][3] = -1e30f;
            }
        }

        float mt0 = -1e30f, mt1 = -1e30f;
#pragma unroll
        for (int c = 0; c < 8; ++c) {
            mt0 = fmaxf(mt0, fmaxf(s[c][0], s[c][1]));
            mt1 = fmaxf(mt1, fmaxf(s[c][2], s[c][3]));
        }
        mt0 = fmaxf(mt0, __shfl_xor_sync(0xffffffffu, mt0, 1));
        mt0 = fmaxf(mt0, __shfl_xor_sync(0xffffffffu, mt0, 2));
        mt1 = fmaxf(mt1, __shfl_xor_sync(0xffffffffu, mt1, 1));
        mt1 = fmaxf(mt1, __shfl_xor_sync(0xffffffffu, mt1, 2));

        float mn0 = fmaxf(m_i[0], mt0), mn1 = fmaxf(m_i[1], mt1);
        float al0 = __expf(m_i[0] - mn0), al1 = __expf(m_i[1] - mn1);
        float sum0 = 0.f, sum1 = 0.f;
#pragma unroll
        for (int c = 0; c < 8; ++c) {
            s[c][0] = __expf(s[c][0] - mn0);
            s[c][1] = __expf(s[c][1] - mn0);
            s[c][2] = __expf(s[c][2] - mn1);
            s[c][3] = __expf(s[c][3] - mn1);
            sum0 += s[c][0] + s[c][1];
            sum1 += s[c][2] + s[c][3];
        }
        sum0 += __shfl_xor_sync(0xffffffffu, sum0, 1);
        sum0 += __shfl_xor_sync(0xffffffffu, sum0, 2);
        sum1 += __shfl_xor_sync(0xffffffffu, sum1, 1);
        sum1 += __shfl_xor_sync(0xffffffffu, sum1, 2);

        l_i[0] = l_i[0] * al0 + sum0;
        l_i[1] = l_i[1] * al1 + sum1;
        m_i[0] = mn0; m_i[1] = mn1;

#pragma unroll
        for (int i = 0; i < 16; ++i) {
            o[i][0] *= al0; o[i][1] *= al0;
            o[i][2] *= al1; o[i][3] *= al1;
        }

#pragma unroll
        for (int j = 0; j < 4; ++j) {
            unsigned aPh[4], aPl[4];
            float p00 = s[2*j][0],   p01 = s[2*j][1],   p02 = s[2*j][2],   p03 = s[2*j][3];
            float p10 = s[2*j+1][0], p11 = s[2*j+1][1], p12 = s[2*j+1][2], p13 = s[2*j+1][3];
            float h00 = __bfloat162float(__float2bfloat16(p00));
            float h01 = __bfloat162float(__float2bfloat16(p01));
            float h02 = __bfloat162float(__float2bfloat16(p02));
            float h03 = __bfloat162float(__float2bfloat16(p03));
            float h10 = __bfloat162float(__float2bfloat16(p10));
            float h11 = __bfloat162float(__float2bfloat16(p11));
            float h12 = __bfloat162float(__float2bfloat16(p12));
            float h13 = __bfloat162float(__float2bfloat16(p13));
            aPh[0] = packbf2(h00, h01);  aPh[1] = packbf2(h02, h03);
            aPh[2] = packbf2(h10, h11);  aPh[3] = packbf2(h12, h13);
            aPl[0] = packbf2(p00 - h00, p01 - h01);
            aPl[1] = packbf2(p02 - h02, p03 - h03);
            aPl[2] = packbf2(p10 - h10, p11 - h11);
            aPl[3] = packbf2(p12 - h12, p13 - h13);

#pragma unroll
            for (int dd = 0; dd < 8; ++dd) {
                unsigned voff = (unsigned)(((j * 16 + vro) * FA_LD + dd * 16 + vco) * 2);
                unsigned h0, h1, h2, h3, q0, q1, q2, q3;
                ldsm_x4t(h0, h1, h2, h3, uVh + voff);
                ldsm_x4t(q0, q1, q2, q3, uVl + voff);
                unsigned bh0[2] = {h0, h1}, bh1[2] = {h2, h3};
                unsigned bl0[2] = {q0, q1}, bl1[2] = {q2, q3};
                mma16816(o[2*dd],   aPh, bh0);
                mma16816(o[2*dd],   aPh, bl0);
                mma16816(o[2*dd],   aPl, bh0);
                mma16816(o[2*dd+1], aPh, bh1);
                mma16816(o[2*dd+1], aPh, bl1);
                mma16816(o[2*dd+1], aPl, bh1);
            }
        }
    }

    float inv0 = 1.f / l_i[0], inv1 = 1.f / l_i[1];
    int trow0 = m0 + w * 16 + g;
#pragma unroll
    for (int c = 0; c < 16; ++c) {
        int gc = h * HD_ + c * 8 + 2 * t4;
        *(float2*)&O[((size_t)(b * T_ + trow0)) * TOT_ + gc] =
            make_float2(o[c][0] * inv0, o[c][1] * inv0);
        *(float2*)&O[((size_t)(b * T_ + trow0 + 8)) * TOT_ + gc] =
            make_float2(o[c][2] * inv1, o[c][3] * inv1);
    }
}

// ---------------- launch ----------------
extern "C" void kernel_launch(void* const* d_in, const int* in_sizes, int n_in,
                              void* d_out, int out_size) {
    const float* x   = (const float*)d_in[0];
    const float* cs  = (const float*)d_in[1];
    const float* sn  = (const float*)d_in[2];
    const float* Wq  = (const float*)d_in[3];
    const float* Wk  = (const float*)d_in[4];
    const float* Wv  = (const float*)d_in[5];
    const float* Wo  = (const float*)d_in[6];
    float* out = (float*)d_out;

    float *qkv, *Og;
    __nv_bfloat16 *xh, *xl, *wqh, *wql, *woh, *wol, *oh, *ol;
    __nv_bfloat16 *Qh, *Ql, *Kh, *Kl, *Vh, *Vl;
    cudaGetSymbolAddress((void**)&qkv, g_qkv);
    cudaGetSymbolAddress((void**)&Og, g_O);
    cudaGetSymbolAddress((void**)&xh, g_xh);
    cudaGetSymbolAddress((void**)&xl, g_xl);
    cudaGetSymbolAddress((void**)&wqh, g_wqh);
    cudaGetSymbolAddress((void**)&wql, g_wql);
    cudaGetSymbolAddress((void**)&woh, g_woh);
    cudaGetSymbolAddress((void**)&wol, g_wol);
    cudaGetSymbolAddress((void**)&oh, g_oh);
    cudaGetSymbolAddress((void**)&ol, g_ol);
    cudaGetSymbolAddress((void**)&Qh, g_Qhh);
    cudaGetSymbolAddress((void**)&Ql, g_Qll);
    cudaGetSymbolAddress((void**)&Kh, g_Khh);
    cudaGetSymbolAddress((void**)&Kl, g_Kll);
    cudaGetSymbolAddress((void**)&Vh, g_Vhh);
    cudaGetSymbolAddress((void**)&Vl, g_Vll);

    cudaFuncSetAttribute(gemm_bf16x3, cudaFuncAttributeMaxDynamicSharedMemorySize, GEMM_SMEM);
    cudaFuncSetAttribute(flash_attn_tc, cudaFuncAttributeMaxDynamicSharedMemorySize, FA_SMEM);

    split_f32<<<(MROWS * DM_ / 4 + 255) / 256, 256>>>(x, xh, xl, MROWS * DM_ / 4);
    split_wqkv<<<(DM_ * NQKV / 4 + 255) / 256, 256>>>(Wq, Wk, Wv, wqh, wql);
    split_f32<<<(TOT_ * DM_ / 4 + 255) / 256, 256>>>(Wo, woh, wol, TOT_ * DM_ / 4);

    dim3 qkvGrid(NQKV / 128, MROWS / 128);
    gemm_bf16x3<<<qkvGrid, 256, GEMM_SMEM>>>(xh, xl, wqh, wql, qkv, NQKV);

    int writeKV = (out_size >= 3 * MAIN_ELEMS) ? 1 : 0;
    float* outK = out + MAIN_ELEMS;
    float* outV = out + 2 * MAIN_ELEMS;
    int ropeThreads = B_ * T_ * H_ * 64;
    rope_split<<<ropeThreads / 256, 256>>>(qkv, cs, sn, Qh, Ql, Kh, Kl, Vh, Vl,
                                           writeKV ? outK : Og,
                                           writeKV ? outV : Og, writeKV);

    dim3 faGrid(T_ / 64, B_ * H_);
    flash_attn_tc<<<faGrid, 128, FA_SMEM>>>(Qh, Ql, Kh, Kl, Vh, Vl, Og);

    split_f32<<<(MROWS * TOT_ / 4 + 255) / 256, 256>>>(Og, oh, ol, MROWS * TOT_ / 4);
    dim3 oGrid(DM_ / 128, MROWS / 128);
    gemm_bf16x3<<<oGrid, 256, GEMM_SMEM>>>(oh, ol, woh, wol, out, DM_);
}

// round 7
// speedup vs baseline: 6.6022x; 2.1617x over previous
#include <cuda_runtime.h>
#include <cuda_fp16.h>
#include <math.h>

// Problem constants
#define B_  2
#define T_  2048
#define DM_ 2048
#define H_  16
#define HD_ 128
#define TOT_ 2048
#define MROWS 4096
#define NQKV 6144
#define GK   2048
#define MAIN_ELEMS (MROWS * DM_)

// ---------------- scratch ----------------
__device__ float g_qkv[MROWS * NQKV];
__device__ float g_O[MROWS * TOT_];
__device__ __align__(16) __half g_xh[MROWS * DM_];
__device__ __align__(16) __half g_wq[DM_ * NQKV];    // fused Wqkv [k][6144]
__device__ __align__(16) __half g_wo[TOT_ * DM_];    // [k][2048]
__device__ __align__(16) __half g_oh[MROWS * TOT_];
__device__ __align__(16) __half g_Q[MROWS * TOT_];   // [b,h,t,hd]
__device__ __align__(16) __half g_K[MROWS * TOT_];
__device__ __align__(16) __half g_V[MROWS * TOT_];

// ---------------- helpers ----------------
__device__ __forceinline__ void ldsm_x4(unsigned& r0, unsigned& r1, unsigned& r2, unsigned& r3,
                                        unsigned addr) {
    asm volatile("ldmatrix.sync.aligned.m8n8.x4.shared.b16 {%0,%1,%2,%3}, [%4];\n"
                 : "=r"(r0), "=r"(r1), "=r"(r2), "=r"(r3) : "r"(addr));
}
__device__ __forceinline__ void ldsm_x4t(unsigned& r0, unsigned& r1, unsigned& r2, unsigned& r3,
                                         unsigned addr) {
    asm volatile("ldmatrix.sync.aligned.m8n8.x4.trans.shared.b16 {%0,%1,%2,%3}, [%4];\n"
                 : "=r"(r0), "=r"(r1), "=r"(r2), "=r"(r3) : "r"(addr));
}
__device__ __forceinline__ void mma16816(float* c, const unsigned* a, const unsigned* b) {
    asm volatile("mma.sync.aligned.m16n8k16.row.col.f32.f16.f16.f32 "
                 "{%0,%1,%2,%3}, {%4,%5,%6,%7}, {%8,%9}, {%0,%1,%2,%3};\n"
                 : "+f"(c[0]), "+f"(c[1]), "+f"(c[2]), "+f"(c[3])
                 : "r"(a[0]), "r"(a[1]), "r"(a[2]), "r"(a[3]), "r"(b[0]), "r"(b[1]));
}
__device__ __forceinline__ unsigned packh2(float x, float y) {
    __half2 h2 = __floats2half2_rn(x, y);
    return *(unsigned*)&h2;
}
__device__ __forceinline__ void cp16(unsigned dst, const void* src) {
    asm volatile("cp.async.ca.shared.global [%0], [%1], 16;\n" :: "r"(dst), "l"(src));
}
__device__ __forceinline__ void cp_commit() {
    asm volatile("cp.async.commit_group;\n" ::: "memory");
}
template <int N>
__device__ __forceinline__ void cp_wait() {
    asm volatile("cp.async.wait_group %0;\n" :: "n"(N) : "memory");
}

// ---------------- fp32 -> fp16 converts ----------------
__global__ __launch_bounds__(256) void conv_f16(const float* __restrict__ src,
                                                __half* __restrict__ dst, int n4) {
    int i = blockIdx.x * blockDim.x + threadIdx.x;
    if (i >= n4) return;
    float4 v = ((const float4*)src)[i];
    uint2 u;
    u.x = packh2(v.x, v.y);
    u.y = packh2(v.z, v.w);
    ((uint2*)dst)[i] = u;
}

__global__ __launch_bounds__(256) void conv_wqkv(const float* __restrict__ Wq,
                                                 const float* __restrict__ Wk,
                                                 const float* __restrict__ Wv,
                                                 __half* __restrict__ dst) {
    int i = blockIdx.x * blockDim.x + threadIdx.x;
    if (i >= DM_ * NQKV / 4) return;
    int k = i / (NQKV / 4);
    int n = (i % (NQKV / 4)) * 4;
    const float* src;
    int nn;
    if (n < 2048)       { src = Wq; nn = n; }
    else if (n < 4096)  { src = Wk; nn = n - 2048; }
    else                { src = Wv; nn = n - 4096; }
    float4 v = *(const float4*)&src[(size_t)k * 2048 + nn];
    uint2 u;
    u.x = packh2(v.x, v.y);
    u.y = packh2(v.z, v.w);
    ((uint2*)dst)[i] = u;
}

// ---------------- fp16 tensor-core GEMM, cp.async double-buffered ----------------
// C[M,N] = A[M,2048] @ B[2048,N]. BM=128 BN=128 BK=32, 256 thr, warp tile 32x64.
#define LDA 40
#define LDB 136
#define ST_A 0
#define ST_B 5120            // 128*40
#define ST_SZ 9472           // halves per stage (18944 B)
#define GEMM_SMEM (2 * ST_SZ * 2)   // 37888 B

__global__ __launch_bounds__(256, 2) void gemm_f16(const __half* __restrict__ A,
                                                   const __half* __restrict__ Bm,
                                                   float* __restrict__ C, int N) {
    extern __shared__ __half sm[];
    const unsigned smu = (unsigned)__cvta_generic_to_shared(sm);
    const int tid = threadIdx.x;
    const int lane = tid & 31, wid = tid >> 5;
    const int wm = wid & 3, wn = wid >> 2;
    const int m0 = blockIdx.y * 128, n0 = blockIdx.x * 128;

    int ar[2], ac[2], br[2], bc[2];
#pragma unroll
    for (int q = 0; q < 2; ++q) {
        int c = tid * 2 + q;
        ar[q] = c >> 2;  ac[q] = (c & 3) << 3;   // A: 128 x 32
        br[q] = c >> 4;  bc[q] = (c & 15) << 3;  // B: 32 x 128
    }

    float acc[2][8][4];
#pragma unroll
    for (int mt = 0; mt < 2; ++mt)
#pragma unroll
        for (int nt = 0; nt < 8; ++nt)
#pragma unroll
            for (int e = 0; e < 4; ++e) acc[mt][nt][e] = 0.f;

    auto prefetch = [&](int s, int k0) {
        unsigned sb = smu + (unsigned)(s * ST_SZ * 2);
#pragma unroll
        for (int q = 0; q < 2; ++q) {
            cp16(sb + (ST_A + ar[q] * LDA + ac[q]) * 2, A + (size_t)(m0 + ar[q]) * GK + k0 + ac[q]);
            cp16(sb + (ST_B + br[q] * LDB + bc[q]) * 2, Bm + (size_t)(k0 + br[q]) * N + n0 + bc[q]);
        }
    };

    prefetch(0, 0);
    cp_commit();
    cp_wait<0>();
    __syncthreads();

    const int lrow = lane & 15;
    const int lcol = (lane >> 4) << 3;
    const int NIT = GK / 32;

    for (int it = 0; it < NIT; ++it) {
        if (it + 1 < NIT) {
            prefetch((it + 1) & 1, (it + 1) * 32);
            cp_commit();
        }

        unsigned sb = smu + (unsigned)((it & 1) * ST_SZ * 2);
        unsigned s_a = sb + ST_A * 2;
        unsigned s_b = sb + ST_B * 2;

#pragma unroll
        for (int ks = 0; ks < 32; ks += 16) {
            unsigned a[2][4];
#pragma unroll
            for (int mt = 0; mt < 2; ++mt) {
                unsigned off = ((wm * 32 + mt * 16 + lrow) * LDA + ks + lcol) * 2;
                ldsm_x4(a[mt][0], a[mt][1], a[mt][2], a[mt][3], s_a + off);
            }
#pragma unroll
            for (int nt2 = 0; nt2 < 4; ++nt2) {
                unsigned off = ((ks + lrow) * LDB + wn * 64 + nt2 * 16 + lcol) * 2;
                unsigned t0, t1, t2, t3;
                ldsm_x4t(t0, t1, t2, t3, s_b + off);
                unsigned b0[2] = {t0, t1}, b1[2] = {t2, t3};
#pragma unroll
                for (int mt = 0; mt < 2; ++mt) {
                    mma16816(acc[mt][2*nt2],   a[mt], b0);
                    mma16816(acc[mt][2*nt2+1], a[mt], b1);
                }
            }
        }
        if (it + 1 < NIT) cp_wait<0>();
        __syncthreads();
    }

    const int erow = lane >> 2;
    const int ecol = (lane & 3) << 1;
#pragma unroll
    for (int mt = 0; mt < 2; ++mt)
#pragma unroll
        for (int nt = 0; nt < 8; ++nt) {
            int gr = m0 + wm * 32 + mt * 16 + erow;
            int gc = n0 + wn * 64 + nt * 8 + ecol;
            *(float2*)&C[(size_t)gr * N + gc]       = make_float2(acc[mt][nt][0], acc[mt][nt][1]);
            *(float2*)&C[(size_t)(gr + 8) * N + gc] = make_float2(acc[mt][nt][2], acc[mt][nt][3]);
        }
}

// ---------------- RoPE + permute + fp16 convert ----------------
// Q pre-scaled by HD^-0.5.
__global__ __launch_bounds__(256) void rope_conv(const float* __restrict__ qkv,
                                                 const float* __restrict__ cosp,
                                                 const float* __restrict__ sinp,
                                                 __half* __restrict__ Qd,
                                                 __half* __restrict__ Kd,
                                                 __half* __restrict__ Vd,
                                                 float* __restrict__ outK,
                                                 float* __restrict__ outV,
                                                 int writeKV) {
    int idx = blockIdx.x * blockDim.x + threadIdx.x;
    int d = idx & 63;
    int h = (idx >> 6) & 15;
    int t = (idx >> 10) & 2047;
    int b = idx >> 21;

    const float scale = 0.08838834764831843f;
    size_t in0 = ((size_t)(b * T_ + t)) * NQKV + h * HD_;
    size_t ob  = (((size_t)(b * H_ + h)) * T_ + t) * HD_;

    float c1 = cosp[t * HD_ + d],      s1 = sinp[t * HD_ + d];
    float c2 = cosp[t * HD_ + d + 64], s2 = sinp[t * HD_ + d + 64];

    float q1 = qkv[in0 + d], q2 = qkv[in0 + d + 64];
    Qd[ob + d]      = __float2half((q1 * c1 - q2 * s1) * scale);
    Qd[ob + d + 64] = __float2half((q2 * c2 + q1 * s2) * scale);

    float k1 = qkv[in0 + 2048 + d], k2 = qkv[in0 + 2048 + d + 64];
    float ko1 = k1 * c1 - k2 * s1;
    float ko2 = k2 * c2 + k1 * s2;
    Kd[ob + d]      = __float2half(ko1);
    Kd[ob + d + 64] = __float2half(ko2);

    float v1 = qkv[in0 + 4096 + d], v2 = qkv[in0 + 4096 + d + 64];
    Vd[ob + d]      = __float2half(v1);
    Vd[ob + d + 64] = __float2half(v2);

    if (writeKV) {
        outK[ob + d] = ko1; outK[ob + d + 64] = ko2;
        outV[ob + d] = v1;  outV[ob + d + 64] = v2;
    }
}

// ---------------- fp16 tensor-core flash attention, causal ----------------
#define FA_LD 136
#define FA_SMEM (3 * 64 * FA_LD * 2)   // 52224 B

__global__ __launch_bounds__(128, 3) void flash_attn_tc(
        const __half* __restrict__ Q_, const __half* __restrict__ K_,
        const __half* __restrict__ V_, float* __restrict__ O) {
    const int qt = blockIdx.x;
    const int bh = blockIdx.y;
    const int b = bh >> 4, h = bh & 15;
    const int m0 = qt * 64;
    const size_t base = (size_t)bh * T_ * HD_;

    extern __shared__ __half sb[];
    __half* sQ = sb;
    __half* sK = sQ + 64 * FA_LD;
    __half* sV = sK + 64 * FA_LD;

    const int tid = threadIdx.x;
    const int lane = tid & 31, w = tid >> 5;
    const int g = lane >> 2, t4 = lane & 3;
    const int l8 = lane & 7, sel = lane >> 3;
    const int aro = l8 + ((sel & 1) ? 8 : 0), aco = (sel & 2) ? 8 : 0;
    const int bro = l8 + ((sel & 2) ? 8 : 0), bco = (sel & 1) ? 8 : 0;
    const int vro = l8 + ((sel & 1) ? 8 : 0), vco = (sel & 2) ? 8 : 0;

    for (int i = tid; i < 64 * 16; i += 128) {
        int r = i >> 4, c = (i & 15) * 8;
        *(uint4*)&sQ[r * FA_LD + c] = *(const uint4*)&Q_[base + (size_t)(m0 + r) * HD_ + c];
    }

    unsigned uQ = (unsigned)__cvta_generic_to_shared(sQ);
    unsigned uK = (unsigned)__cvta_generic_to_shared(sK);
    unsigned uV = (unsigned)__cvta_generic_to_shared(sV);

    float o[16][4];
#pragma unroll
    for (int i = 0; i < 16; ++i)
#pragma unroll
        for (int e = 0; e < 4; ++e) o[i][e] = 0.f;
    float m_i[2] = {-1e30f, -1e30f};
    float l_i[2] = {0.f, 0.f};

    for (int tt = 0; tt <= qt; ++tt) {
        const int n0 = tt * 64;
        __syncthreads();
        for (int i = tid; i < 64 * 16; i += 128) {
            int r = i >> 4, c = (i & 15) * 8;
            size_t goff = base + (size_t)(n0 + r) * HD_ + c;
            *(uint4*)&sK[r * FA_LD + c] = *(const uint4*)&K_[goff];
            *(uint4*)&sV[r * FA_LD + c] = *(const uint4*)&V_[goff];
        }
        __syncthreads();

        float s[8][4];
#pragma unroll
        for (int c = 0; c < 8; ++c)
#pragma unroll
            for (int e = 0; e < 4; ++e) s[c][e] = 0.f;

#pragma unroll
        for (int kk = 0; kk < 8; ++kk) {
            unsigned a[4];
            unsigned qoff = (unsigned)(((w * 16 + aro) * FA_LD + kk * 16 + aco) * 2);
            ldsm_x4(a[0], a[1], a[2], a[3], uQ + qoff);
#pragma unroll
            for (int nc = 0; nc < 4; ++nc) {
                unsigned koff = (unsigned)(((nc * 16 + bro) * FA_LD + kk * 16 + bco) * 2);
                unsigned t0, t1, t2, t3;
                ldsm_x4(t0, t1, t2, t3, uK + koff);
                unsigned b0[2] = {t0, t1}, b1[2] = {t2, t3};
                mma16816(s[2*nc],   a, b0);
                mma16816(s[2*nc+1], a, b1);
            }
        }

        if (tt == qt) {
            int r0 = m0 + w * 16 + g, r1 = r0 + 8;
#pragma unroll
            for (int c = 0; c < 8; ++c) {
                int col = n0 + c * 8 + 2 * t4;
                if (col     > r0) s[c][0] = -1e30f;
                if (col + 1 > r0) s[c][1] = -1e30f;
                if (col     > r1) s[c][2] = -1e30f;
                if (col + 1 > r1) s[c][3] = -1e30f;
            }
        }

        float mt0 = -1e30f, mt1 = -1e30f;
#pragma unroll
        for (int c = 0; c < 8; ++c) {
            mt0 = fmaxf(mt0, fmaxf(s[c][0], s[c][1]));
            mt1 = fmaxf(mt1, fmaxf(s[c][2], s[c][3]));
        }
        mt0 = fmaxf(mt0, __shfl_xor_sync(0xffffffffu, mt0, 1));
        mt0 = fmaxf(mt0, __shfl_xor_sync(0xffffffffu, mt0, 2));
        mt1 = fmaxf(mt1, __shfl_xor_sync(0xffffffffu, mt1, 1));
        mt1 = fmaxf(mt1, __shfl_xor_sync(0xffffffffu, mt1, 2));

        float mn0 = fmaxf(m_i[0], mt0), mn1 = fmaxf(m_i[1], mt1);
        float al0 = __expf(m_i[0] - mn0), al1 = __expf(m_i[1] - mn1);
        float sum0 = 0.f, sum1 = 0.f;
#pragma unroll
        for (int c = 0; c < 8; ++c) {
            s[c][0] = __expf(s[c][0] - mn0);
            s[c][1] = __expf(s[c][1] - mn0);
            s[c][2] = __expf(s[c][2] - mn1);
            s[c][3] = __expf(s[c][3] - mn1);
            sum0 += s[c][0] + s[c][1];
            sum1 += s[c][2] + s[c][3];
        }
        sum0 += __shfl_xor_sync(0xffffffffu, sum0, 1);
        sum0 += __shfl_xor_sync(0xffffffffu, sum0, 2);
        sum1 += __shfl_xor_sync(0xffffffffu, sum1, 1);
        sum1 += __shfl_xor_sync(0xffffffffu, sum1, 2);

        l_i[0] = l_i[0] * al0 + sum0;
        l_i[1] = l_i[1] * al1 + sum1;
        m_i[0] = mn0; m_i[1] = mn1;

#pragma unroll
        for (int i = 0; i < 16; ++i) {
            o[i][0] *= al0; o[i][1] *= al0;
            o[i][2] *= al1; o[i][3] *= al1;
        }

#pragma unroll
        for (int j = 0; j < 4; ++j) {
            unsigned aP[4];
            aP[0] = packh2(s[2*j][0],   s[2*j][1]);
            aP[1] = packh2(s[2*j][2],   s[2*j][3]);
            aP[2] = packh2(s[2*j+1][0], s[2*j+1][1]);
            aP[3] = packh2(s[2*j+1][2], s[2*j+1][3]);

#pragma unroll
            for (int dd = 0; dd < 8; ++dd) {
                unsigned voff = (unsigned)(((j * 16 + vro) * FA_LD + dd * 16 + vco) * 2);
                unsigned t0, t1, t2, t3;
                ldsm_x4t(t0, t1, t2, t3, uV + voff);
                unsigned b0[2] = {t0, t1}, b1[2] = {t2, t3};
                mma16816(o[2*dd],   aP, b0);
                mma16816(o[2*dd+1], aP, b1);
            }
        }
    }

    float inv0 = 1.f / l_i[0], inv1 = 1.f / l_i[1];
    int trow0 = m0 + w * 16 + g;
#pragma unroll
    for (int c = 0; c < 16; ++c) {
        int gc = h * HD_ + c * 8 + 2 * t4;
        *(float2*)&O[((size_t)(b * T_ + trow0)) * TOT_ + gc] =
            make_float2(o[c][0] * inv0, o[c][1] * inv0);
        *(float2*)&O[((size_t)(b * T_ + trow0 + 8)) * TOT_ + gc] =
            make_float2(o[c][2] * inv1, o[c][3] * inv1);
    }
}

// ---------------- launch ----------------
extern "C" void kernel_launch(void* const* d_in, const int* in_sizes, int n_in,
                              void* d_out, int out_size) {
    const float* x   = (const float*)d_in[0];
    const float* cs  = (const float*)d_in[1];
    const float* sn  = (const float*)d_in[2];
    const float* Wq  = (const float*)d_in[3];
    const float* Wk  = (const float*)d_in[4];
    const float* Wv  = (const float*)d_in[5];
    const float* Wo  = (const float*)d_in[6];
    float* out = (float*)d_out;

    float *qkv, *Og;
    __half *xh, *wq, *wo, *oh, *Qd, *Kd, *Vd;
    cudaGetSymbolAddress((void**)&qkv, g_qkv);
    cudaGetSymbolAddress((void**)&Og, g_O);
    cudaGetSymbolAddress((void**)&xh, g_xh);
    cudaGetSymbolAddress((void**)&wq, g_wq);
    cudaGetSymbolAddress((void**)&wo, g_wo);
    cudaGetSymbolAddress((void**)&oh, g_oh);
    cudaGetSymbolAddress((void**)&Qd, g_Q);
    cudaGetSymbolAddress((void**)&Kd, g_K);
    cudaGetSymbolAddress((void**)&Vd, g_V);

    cudaFuncSetAttribute(gemm_f16, cudaFuncAttributeMaxDynamicSharedMemorySize, GEMM_SMEM);
    cudaFuncSetAttribute(flash_attn_tc, cudaFuncAttributeMaxDynamicSharedMemorySize, FA_SMEM);

    // converts
    conv_f16<<<(MROWS * DM_ / 4 + 255) / 256, 256>>>(x, xh, MROWS * DM_ / 4);
    conv_wqkv<<<(DM_ * NQKV / 4 + 255) / 256, 256>>>(Wq, Wk, Wv, wq);
    conv_f16<<<(TOT_ * DM_ / 4 + 255) / 256, 256>>>(Wo, wo, TOT_ * DM_ / 4);

    // fused QKV projection
    dim3 qkvGrid(NQKV / 128, MROWS / 128);   // (48, 32)
    gemm_f16<<<qkvGrid, 256, GEMM_SMEM>>>(xh, wq, qkv, NQKV);

    int writeKV = (out_size >= 3 * MAIN_ELEMS) ? 1 : 0;
    float* outK = out + MAIN_ELEMS;
    float* outV = out + 2 * MAIN_ELEMS;
    int ropeThreads = B_ * T_ * H_ * 64;
    rope_conv<<<ropeThreads / 256, 256>>>(qkv, cs, sn, Qd, Kd, Vd,
                                          writeKV ? outK : Og,
                                          writeKV ? outV : Og, writeKV);

    dim3 faGrid(T_ / 64, B_ * H_);
    flash_attn_tc<<<faGrid, 128, FA_SMEM>>>(Qd, Kd, Vd, Og);

    conv_f16<<<(MROWS * TOT_ / 4 + 255) / 256, 256>>>(Og, oh, MROWS * TOT_ / 4);
    dim3 oGrid(DM_ / 128, MROWS / 128);
    gemm_f16<<<oGrid, 256, GEMM_SMEM>>>(oh, wo, out, DM_);
}